// round 8
// baseline (speedup 1.0000x reference)
#include <cuda_runtime.h>
#include <math.h>

// Problem constants
#define B_   4
#define L_   2048
#define D_   1024
#define H_   16
#define HD_  64
#define BH_  (B_*H_)
#define BL_  (B_*L_)
#define SCALE_ 0.125f   // 1/sqrt(64)

// ---------------- scratch (device globals; no allocation allowed) ----------
__device__ float g_qp [BL_ * D_];          // q projection  [b*l][1024]
__device__ float g_kvp[BL_ * 2 * D_];      // kv projection [b*l][2048]
__device__ float g_q  [BH_ * L_ * HD_];    // [b,h,l,hd] after rope
__device__ float g_k  [BH_ * L_ * HD_];
__device__ float g_v  [BH_ * L_ * HD_];
__device__ float g_attn[BL_ * D_];         // [b,l,h*hd]

// ---------------- fp32 SGEMM: C[M,N] = A[M,K] @ W[K,N] + bias --------------
// 128x128 tile, BK=8, 256 threads, 8x8 per thread.
__global__ void __launch_bounds__(256) sgemm_bias_kernel(
    const float* __restrict__ A, const float* __restrict__ W,
    const float* __restrict__ bias, float* __restrict__ C,
    int M, int N, int K)
{
    __shared__ float As[8][128];
    __shared__ float Bs[8][128];
    const int tid = threadIdx.x;
    const int tx = tid & 15, ty = tid >> 4;
    const int m0 = blockIdx.y << 7, n0 = blockIdx.x << 7;

    const int arow = tid >> 1;          // 0..127
    const int acol = (tid & 1) << 2;    // 0 or 4
    const int brow = tid >> 5;          // 0..7
    const int bcol = (tid & 31) << 2;   // 0..124

    const float* Ap = A + (size_t)(m0 + arow) * K + acol;
    const float* Wp = W + (size_t)brow * N + n0 + bcol;

    float acc[8][8];
#pragma unroll
    for (int i = 0; i < 8; i++)
#pragma unroll
        for (int j = 0; j < 8; j++) acc[i][j] = 0.f;

    for (int kt = 0; kt < K; kt += 8) {
        float4 av = *(const float4*)(Ap + kt);
        float4 bv = *(const float4*)(Wp + (size_t)kt * N);
        As[acol + 0][arow] = av.x;
        As[acol + 1][arow] = av.y;
        As[acol + 2][arow] = av.z;
        As[acol + 3][arow] = av.w;
        *(float4*)&Bs[brow][bcol] = bv;
        __syncthreads();
#pragma unroll
        for (int k = 0; k < 8; k++) {
            float4 a0 = *(const float4*)&As[k][ty << 3];
            float4 a1 = *(const float4*)&As[k][(ty << 3) + 4];
            float4 b0 = *(const float4*)&Bs[k][tx << 3];
            float4 b1 = *(const float4*)&Bs[k][(tx << 3) + 4];
            float a[8]  = {a0.x, a0.y, a0.z, a0.w, a1.x, a1.y, a1.z, a1.w};
            float bb[8] = {b0.x, b0.y, b0.z, b0.w, b1.x, b1.y, b1.z, b1.w};
#pragma unroll
            for (int i = 0; i < 8; i++)
#pragma unroll
                for (int j = 0; j < 8; j++)
                    acc[i][j] = fmaf(a[i], bb[j], acc[i][j]);
        }
        __syncthreads();
    }

    float bj[8];
#pragma unroll
    for (int j = 0; j < 8; j++) bj[j] = bias[n0 + (tx << 3) + j];
#pragma unroll
    for (int i = 0; i < 8; i++) {
        size_t row = (size_t)(m0 + (ty << 3) + i);
        float* Cp = C + row * N + n0 + (tx << 3);
        float4 o0 = make_float4(acc[i][0] + bj[0], acc[i][1] + bj[1],
                                acc[i][2] + bj[2], acc[i][3] + bj[3]);
        float4 o1 = make_float4(acc[i][4] + bj[4], acc[i][5] + bj[5],
                                acc[i][6] + bj[6], acc[i][7] + bj[7]);
        *(float4*)(Cp)     = o0;
        *(float4*)(Cp + 4) = o1;
    }
}

// ---------------- RoPE + head split/transpose ------------------------------
// One thread per (b,h,l,pair). rope[l, 2i] = sin, rope[l, 2i+1] = cos.
// Writes g_q/g_k/g_v in [b,h,l,hd] layout.
__global__ void __launch_bounds__(256) rope_split_kernel(const float* __restrict__ rope)
{
    int t = blockIdx.x * 256 + threadIdx.x;   // 0 .. B*H*L*32-1
    int i = t & 31;
    int l = (t >> 5) & (L_ - 1);
    int h = (t >> 16) & (H_ - 1);
    int b = t >> 20;

    float2 rp = ((const float2*)rope)[l * 32 + i];
    float sn = rp.x, cs = rp.y;

    const float2* qp2 = (const float2*)g_qp;
    const float2* kv2 = (const float2*)g_kvp;
    float2 q = qp2[(size_t)(b * L_ + l) * 512 + h * 32 + i];
    size_t kvbase = (size_t)(b * L_ + l) * 1024;
    float2 k = kv2[kvbase + h * 32 + i];
    float2 v = kv2[kvbase + 512 + h * 32 + i];

    float2 qo, ko;
    qo.x = q.x * cs - q.y * sn;  qo.y = q.x * sn + q.y * cs;
    ko.x = k.x * cs - k.y * sn;  ko.y = k.x * sn + k.y * cs;

    size_t o = (size_t)((b * H_ + h) * L_ + l) * 32 + i;
    ((float2*)g_q)[o] = qo;
    ((float2*)g_k)[o] = ko;
    ((float2*)g_v)[o] = v;
}

// ---------------- causal flash attention (fp32 SIMT) -----------------------
// BM=BN=64, HD=64. 256 threads = 16x16, 4x4 outputs/thread.
#define FBM 64
#define FBN 64
#define FPAD 68
#define FLASH_SMEM ((64*FPAD /*Qt*/ + 64*FPAD /*Kt*/ + FBN*64 /*V*/ + FBM*FPAD /*P*/) * 4)

__global__ void __launch_bounds__(256) flash_kernel()
{
    extern __shared__ float sm[];
    float (*sQt)[FPAD] = (float(*)[FPAD])sm;                       // [hd][row]
    float (*sKt)[FPAD] = (float(*)[FPAD])(sm + 64 * FPAD);         // [hd][col]
    float (*sV)[64]    = (float(*)[64])  (sm + 2 * 64 * FPAD);     // [n][hd]
    float (*sP)[FPAD]  = (float(*)[FPAD])(sm + 2 * 64 * FPAD + FBN * 64);

    const int tid = threadIdx.x;
    const int tx = tid & 15, ty = tid >> 4;
    const int qb = blockIdx.x;            // query block (32)
    const int bh = blockIdx.y;            // 0..63
    const int q0 = qb * FBM;
    const int b = bh >> 4, h = bh & 15;

    const float* Qb = g_q + ((size_t)bh * L_ + q0) * HD_;
    const float* Kb = g_k + (size_t)bh * L_ * HD_;
    const float* Vb = g_v + (size_t)bh * L_ * HD_;

    // Q tile -> transposed smem (once per block)
#pragma unroll
    for (int u = 0; u < 4; u++) {
        int idx = tid + 256 * u;
        int r = idx >> 4;
        int c = (idx & 15) << 2;
        float4 qv = *(const float4*)(Qb + (size_t)r * HD_ + c);
        sQt[c + 0][r] = qv.x; sQt[c + 1][r] = qv.y;
        sQt[c + 2][r] = qv.z; sQt[c + 3][r] = qv.w;
    }

    float m_i[4], l_i[4], Oa[4][4];
#pragma unroll
    for (int i = 0; i < 4; i++) {
        m_i[i] = -INFINITY; l_i[i] = 0.f;
#pragma unroll
        for (int j = 0; j < 4; j++) Oa[i][j] = 0.f;
    }

    for (int kb = 0; kb <= qb; kb++) {
        const int n0 = kb * FBN;
        // K tile transposed + V tile natural
#pragma unroll
        for (int u = 0; u < 4; u++) {
            int idx = tid + 256 * u;
            int r = idx >> 4;
            int c = (idx & 15) << 2;
            float4 kv = *(const float4*)(Kb + (size_t)(n0 + r) * HD_ + c);
            sKt[c + 0][r] = kv.x; sKt[c + 1][r] = kv.y;
            sKt[c + 2][r] = kv.z; sKt[c + 3][r] = kv.w;
            float4 vv = *(const float4*)(Vb + (size_t)(n0 + r) * HD_ + c);
            *(float4*)&sV[r][c] = vv;
        }
        __syncthreads();

        // S = Q K^T (4x4 per thread)
        float S[4][4];
#pragma unroll
        for (int i = 0; i < 4; i++)
#pragma unroll
            for (int j = 0; j < 4; j++) S[i][j] = 0.f;

#pragma unroll 8
        for (int kk = 0; kk < HD_; kk++) {
            float4 a  = *(const float4*)&sQt[kk][ty << 2];
            float4 bb = *(const float4*)&sKt[kk][tx << 2];
            float av[4] = {a.x, a.y, a.z, a.w};
            float bv[4] = {bb.x, bb.y, bb.z, bb.w};
#pragma unroll
            for (int i = 0; i < 4; i++)
#pragma unroll
                for (int j = 0; j < 4; j++)
                    S[i][j] = fmaf(av[i], bv[j], S[i][j]);
        }

        const bool diag = (kb == qb);
#pragma unroll
        for (int i = 0; i < 4; i++) {
            int row = q0 + (ty << 2) + i;
#pragma unroll
            for (int j = 0; j < 4; j++) {
                float s = S[i][j] * SCALE_;
                if (diag && (n0 + (tx << 2) + j > row)) s = -1e9f;
                S[i][j] = s;
            }
        }

        // online softmax; rows are shared by the 16 tx-lanes (shuffle width 16)
#pragma unroll
        for (int i = 0; i < 4; i++) {
            float rm = fmaxf(fmaxf(S[i][0], S[i][1]), fmaxf(S[i][2], S[i][3]));
#pragma unroll
            for (int off = 8; off >= 1; off >>= 1)
                rm = fmaxf(rm, __shfl_xor_sync(0xffffffffu, rm, off, 16));
            float mn = fmaxf(m_i[i], rm);
            float corr = __expf(m_i[i] - mn);
            float ps = 0.f;
#pragma unroll
            for (int j = 0; j < 4; j++) {
                float p = __expf(S[i][j] - mn);
                S[i][j] = p;
                ps += p;
            }
#pragma unroll
            for (int off = 8; off >= 1; off >>= 1)
                ps += __shfl_xor_sync(0xffffffffu, ps, off, 16);
            l_i[i] = l_i[i] * corr + ps;
            m_i[i] = mn;
#pragma unroll
            for (int j = 0; j < 4; j++) Oa[i][j] *= corr;
            *(float4*)&sP[(ty << 2) + i][tx << 2] =
                make_float4(S[i][0], S[i][1], S[i][2], S[i][3]);
        }
        __syncthreads();

        // O += P @ V
#pragma unroll 4
        for (int n4 = 0; n4 < FBN; n4 += 4) {
            float4 p0 = *(const float4*)&sP[(ty << 2) + 0][n4];
            float4 p1 = *(const float4*)&sP[(ty << 2) + 1][n4];
            float4 p2 = *(const float4*)&sP[(ty << 2) + 2][n4];
            float4 p3 = *(const float4*)&sP[(ty << 2) + 3][n4];
            float4 v0 = *(const float4*)&sV[n4 + 0][tx << 2];
            float4 v1 = *(const float4*)&sV[n4 + 1][tx << 2];
            float4 v2 = *(const float4*)&sV[n4 + 2][tx << 2];
            float4 v3 = *(const float4*)&sV[n4 + 3][tx << 2];
            float pr[4][4] = {{p0.x,p0.y,p0.z,p0.w},{p1.x,p1.y,p1.z,p1.w},
                              {p2.x,p2.y,p2.z,p2.w},{p3.x,p3.y,p3.z,p3.w}};
            float vr[4][4] = {{v0.x,v0.y,v0.z,v0.w},{v1.x,v1.y,v1.z,v1.w},
                              {v2.x,v2.y,v2.z,v2.w},{v3.x,v3.y,v3.z,v3.w}};
#pragma unroll
            for (int i = 0; i < 4; i++)
#pragma unroll
                for (int j = 0; j < 4; j++) {
                    float acc = Oa[i][j];
#pragma unroll
                    for (int n = 0; n < 4; n++)
                        acc = fmaf(pr[i][n], vr[n][j], acc);
                    Oa[i][j] = acc;
                }
        }
        __syncthreads();
    }

    // normalize + write [b,l,h*hd]
#pragma unroll
    for (int i = 0; i < 4; i++) {
        int row = q0 + (ty << 2) + i;
        float inv = 1.f / l_i[i];
        float4 o = make_float4(Oa[i][0] * inv, Oa[i][1] * inv,
                               Oa[i][2] * inv, Oa[i][3] * inv);
        *(float4*)&g_attn[(size_t)(b * L_ + row) * D_ + h * HD_ + (tx << 2)] = o;
    }
}

// ---------------- launch ----------------------------------------------------
extern "C" void kernel_launch(void* const* d_in, const int* in_sizes, int n_in,
                              void* d_out, int out_size)
{
    const float* q_in = (const float*)d_in[0];
    const float* k_in = (const float*)d_in[1];
    // d_in[2] = v_in (unused by reference), d_in[3] = mask (tril, hardcoded causal)
    const float* rope = (const float*)d_in[4];
    const float* Wq   = (const float*)d_in[5];
    const float* bq   = (const float*)d_in[6];
    const float* Wkv  = (const float*)d_in[7];
    const float* bkv  = (const float*)d_in[8];
    const float* Wp   = (const float*)d_in[9];
    const float* bp   = (const float*)d_in[10];
    float* out = (float*)d_out;

    float *qp, *kvp, *attn;
    cudaGetSymbolAddress((void**)&qp,   g_qp);
    cudaGetSymbolAddress((void**)&kvp,  g_kvp);
    cudaGetSymbolAddress((void**)&attn, g_attn);

    // 1) Q projection: [8192,1024] = q_in @ Wq + bq
    sgemm_bias_kernel<<<dim3(D_ / 128, BL_ / 128), 256>>>(q_in, Wq, bq, qp, BL_, D_, D_);
    // 2) KV projection: [8192,2048] = k_in @ Wkv + bkv
    sgemm_bias_kernel<<<dim3(2 * D_ / 128, BL_ / 128), 256>>>(k_in, Wkv, bkv, kvp, BL_, 2 * D_, D_);
    // 3) RoPE + split + transpose to [b,h,l,hd]
    rope_split_kernel<<<(B_ * H_ * L_ * 32) / 256, 256>>>(rope);
    // 4) causal flash attention
    cudaFuncSetAttribute(flash_kernel, cudaFuncAttributeMaxDynamicSharedMemorySize, FLASH_SMEM);
    flash_kernel<<<dim3(L_ / FBM, BH_), 256, FLASH_SMEM>>>();
    // 5) output projection: out = attn @ Wp + bp
    sgemm_bias_kernel<<<dim3(D_ / 128, BL_ / 128), 256>>>(attn, Wp, bp, out, BL_, D_, D_);
}

// round 9
// speedup vs baseline: 1.0019x; 1.0019x over previous
#include <cuda_runtime.h>
#include <math.h>

// Problem constants
#define B_   4
#define L_   2048
#define D_   1024
#define H_   16
#define HD_  64
#define BH_  (B_*H_)
#define BL_  (B_*L_)
#define SCALE_ 0.125f   // 1/sqrt(64)

// ---------------- scratch (device globals; no allocation allowed) ----------
__device__ float g_qp [BL_ * D_];          // q projection  [b*l][1024]
__device__ float g_kvp[BL_ * 2 * D_];      // kv projection [b*l][2048]
__device__ float g_q  [BH_ * L_ * HD_];    // [b,h,l,hd] after rope
__device__ float g_k  [BH_ * L_ * HD_];
__device__ float g_v  [BH_ * L_ * HD_];
__device__ float g_attn[BL_ * D_];         // [b,l,h*hd]

// ---------------- fp32 SGEMM: C[M,N] = A[M,K] @ W[K,N] + bias --------------
// 128x128 tile, BK=8, 256 threads, 8x8 per thread.
__global__ void __launch_bounds__(256) sgemm_bias_kernel(
    const float* __restrict__ A, const float* __restrict__ W,
    const float* __restrict__ bias, float* __restrict__ C,
    int M, int N, int K)
{
    __shared__ float As[8][128];
    __shared__ float Bs[8][128];
    const int tid = threadIdx.x;
    const int tx = tid & 15, ty = tid >> 4;
    const int m0 = blockIdx.y << 7, n0 = blockIdx.x << 7;

    const int arow = tid >> 1;          // 0..127
    const int acol = (tid & 1) << 2;    // 0 or 4
    const int brow = tid >> 5;          // 0..7
    const int bcol = (tid & 31) << 2;   // 0..124

    const float* Ap = A + (size_t)(m0 + arow) * K + acol;
    const float* Wp = W + (size_t)brow * N + n0 + bcol;

    float acc[8][8];
#pragma unroll
    for (int i = 0; i < 8; i++)
#pragma unroll
        for (int j = 0; j < 8; j++) acc[i][j] = 0.f;

    for (int kt = 0; kt < K; kt += 8) {
        float4 av = *(const float4*)(Ap + kt);
        float4 bv = *(const float4*)(Wp + (size_t)kt * N);
        As[acol + 0][arow] = av.x;
        As[acol + 1][arow] = av.y;
        As[acol + 2][arow] = av.z;
        As[acol + 3][arow] = av.w;
        *(float4*)&Bs[brow][bcol] = bv;
        __syncthreads();
#pragma unroll
        for (int k = 0; k < 8; k++) {
            float4 a0 = *(const float4*)&As[k][ty << 3];
            float4 a1 = *(const float4*)&As[k][(ty << 3) + 4];
            float4 b0 = *(const float4*)&Bs[k][tx << 3];
            float4 b1 = *(const float4*)&Bs[k][(tx << 3) + 4];
            float a[8]  = {a0.x, a0.y, a0.z, a0.w, a1.x, a1.y, a1.z, a1.w};
            float bb[8] = {b0.x, b0.y, b0.z, b0.w, b1.x, b1.y, b1.z, b1.w};
#pragma unroll
            for (int i = 0; i < 8; i++)
#pragma unroll
                for (int j = 0; j < 8; j++)
                    acc[i][j] = fmaf(a[i], bb[j], acc[i][j]);
        }
        __syncthreads();
    }

    float bj[8];
#pragma unroll
    for (int j = 0; j < 8; j++) bj[j] = bias[n0 + (tx << 3) + j];
#pragma unroll
    for (int i = 0; i < 8; i++) {
        size_t row = (size_t)(m0 + (ty << 3) + i);
        float* Cp = C + row * N + n0 + (tx << 3);
        float4 o0 = make_float4(acc[i][0] + bj[0], acc[i][1] + bj[1],
                                acc[i][2] + bj[2], acc[i][3] + bj[3]);
        float4 o1 = make_float4(acc[i][4] + bj[4], acc[i][5] + bj[5],
                                acc[i][6] + bj[6], acc[i][7] + bj[7]);
        *(float4*)(Cp)     = o0;
        *(float4*)(Cp + 4) = o1;
    }
}

// ---------------- RoPE + head split/transpose ------------------------------
// One thread per (b,h,l,pair). rope[l, 2i] = sin, rope[l, 2i+1] = cos.
// Writes g_q/g_k/g_v in [b,h,l,hd] layout.
__global__ void __launch_bounds__(256) rope_split_kernel(const float* __restrict__ rope)
{
    int t = blockIdx.x * 256 + threadIdx.x;   // 0 .. B*H*L*32-1
    int i = t & 31;
    int l = (t >> 5) & (L_ - 1);
    int h = (t >> 16) & (H_ - 1);
    int b = t >> 20;

    float2 rp = ((const float2*)rope)[l * 32 + i];
    float sn = rp.x, cs = rp.y;

    const float2* qp2 = (const float2*)g_qp;
    const float2* kv2 = (const float2*)g_kvp;
    float2 q = qp2[(size_t)(b * L_ + l) * 512 + h * 32 + i];
    size_t kvbase = (size_t)(b * L_ + l) * 1024;
    float2 k = kv2[kvbase + h * 32 + i];
    float2 v = kv2[kvbase + 512 + h * 32 + i];

    float2 qo, ko;
    qo.x = q.x * cs - q.y * sn;  qo.y = q.x * sn + q.y * cs;
    ko.x = k.x * cs - k.y * sn;  ko.y = k.x * sn + k.y * cs;

    size_t o = (size_t)((b * H_ + h) * L_ + l) * 32 + i;
    ((float2*)g_q)[o] = qo;
    ((float2*)g_k)[o] = ko;
    ((float2*)g_v)[o] = v;
}

// ---------------- causal flash attention (fp32 SIMT) -----------------------
// BM=BN=64, HD=64. 256 threads = 16x16, 4x4 outputs/thread.
#define FBM 64
#define FBN 64
#define FPAD 68
#define FLASH_SMEM ((64*FPAD /*Qt*/ + 64*FPAD /*Kt*/ + FBN*64 /*V*/ + FBM*FPAD /*P*/) * 4)

__global__ void __launch_bounds__(256) flash_kernel()
{
    extern __shared__ float sm[];
    float (*sQt)[FPAD] = (float(*)[FPAD])sm;                       // [hd][row]
    float (*sKt)[FPAD] = (float(*)[FPAD])(sm + 64 * FPAD);         // [hd][col]
    float (*sV)[64]    = (float(*)[64])  (sm + 2 * 64 * FPAD);     // [n][hd]
    float (*sP)[FPAD]  = (float(*)[FPAD])(sm + 2 * 64 * FPAD + FBN * 64);

    const int tid = threadIdx.x;
    const int tx = tid & 15, ty = tid >> 4;
    const int qb = blockIdx.x;            // query block (32)
    const int bh = blockIdx.y;            // 0..63
    const int q0 = qb * FBM;
    const int b = bh >> 4, h = bh & 15;

    const float* Qb = g_q + ((size_t)bh * L_ + q0) * HD_;
    const float* Kb = g_k + (size_t)bh * L_ * HD_;
    const float* Vb = g_v + (size_t)bh * L_ * HD_;

    // Q tile -> transposed smem (once per block)
#pragma unroll
    for (int u = 0; u < 4; u++) {
        int idx = tid + 256 * u;
        int r = idx >> 4;
        int c = (idx & 15) << 2;
        float4 qv = *(const float4*)(Qb + (size_t)r * HD_ + c);
        sQt[c + 0][r] = qv.x; sQt[c + 1][r] = qv.y;
        sQt[c + 2][r] = qv.z; sQt[c + 3][r] = qv.w;
    }

    float m_i[4], l_i[4], Oa[4][4];
#pragma unroll
    for (int i = 0; i < 4; i++) {
        m_i[i] = -INFINITY; l_i[i] = 0.f;
#pragma unroll
        for (int j = 0; j < 4; j++) Oa[i][j] = 0.f;
    }

    for (int kb = 0; kb <= qb; kb++) {
        const int n0 = kb * FBN;
        // K tile transposed + V tile natural
#pragma unroll
        for (int u = 0; u < 4; u++) {
            int idx = tid + 256 * u;
            int r = idx >> 4;
            int c = (idx & 15) << 2;
            float4 kv = *(const float4*)(Kb + (size_t)(n0 + r) * HD_ + c);
            sKt[c + 0][r] = kv.x; sKt[c + 1][r] = kv.y;
            sKt[c + 2][r] = kv.z; sKt[c + 3][r] = kv.w;
            float4 vv = *(const float4*)(Vb + (size_t)(n0 + r) * HD_ + c);
            *(float4*)&sV[r][c] = vv;
        }
        __syncthreads();

        // S = Q K^T (4x4 per thread)
        float S[4][4];
#pragma unroll
        for (int i = 0; i < 4; i++)
#pragma unroll
            for (int j = 0; j < 4; j++) S[i][j] = 0.f;

#pragma unroll 8
        for (int kk = 0; kk < HD_; kk++) {
            float4 a  = *(const float4*)&sQt[kk][ty << 2];
            float4 bb = *(const float4*)&sKt[kk][tx << 2];
            float av[4] = {a.x, a.y, a.z, a.w};
            float bv[4] = {bb.x, bb.y, bb.z, bb.w};
#pragma unroll
            for (int i = 0; i < 4; i++)
#pragma unroll
                for (int j = 0; j < 4; j++)
                    S[i][j] = fmaf(av[i], bv[j], S[i][j]);
        }

        const bool diag = (kb == qb);
#pragma unroll
        for (int i = 0; i < 4; i++) {
            int row = q0 + (ty << 2) + i;
#pragma unroll
            for (int j = 0; j < 4; j++) {
                float s = S[i][j] * SCALE_;
                if (diag && (n0 + (tx << 2) + j > row)) s = -1e9f;
                S[i][j] = s;
            }
        }

        // online softmax; rows are shared by the 16 tx-lanes (shuffle width 16)
#pragma unroll
        for (int i = 0; i < 4; i++) {
            float rm = fmaxf(fmaxf(S[i][0], S[i][1]), fmaxf(S[i][2], S[i][3]));
#pragma unroll
            for (int off = 8; off >= 1; off >>= 1)
                rm = fmaxf(rm, __shfl_xor_sync(0xffffffffu, rm, off, 16));
            float mn = fmaxf(m_i[i], rm);
            float corr = __expf(m_i[i] - mn);
            float ps = 0.f;
#pragma unroll
            for (int j = 0; j < 4; j++) {
                float p = __expf(S[i][j] - mn);
                S[i][j] = p;
                ps += p;
            }
#pragma unroll
            for (int off = 8; off >= 1; off >>= 1)
                ps += __shfl_xor_sync(0xffffffffu, ps, off, 16);
            l_i[i] = l_i[i] * corr + ps;
            m_i[i] = mn;
#pragma unroll
            for (int j = 0; j < 4; j++) Oa[i][j] *= corr;
            *(float4*)&sP[(ty << 2) + i][tx << 2] =
                make_float4(S[i][0], S[i][1], S[i][2], S[i][3]);
        }
        __syncthreads();

        // O += P @ V
#pragma unroll 4
        for (int n4 = 0; n4 < FBN; n4 += 4) {
            float4 p0 = *(const float4*)&sP[(ty << 2) + 0][n4];
            float4 p1 = *(const float4*)&sP[(ty << 2) + 1][n4];
            float4 p2 = *(const float4*)&sP[(ty << 2) + 2][n4];
            float4 p3 = *(const float4*)&sP[(ty << 2) + 3][n4];
            float4 v0 = *(const float4*)&sV[n4 + 0][tx << 2];
            float4 v1 = *(const float4*)&sV[n4 + 1][tx << 2];
            float4 v2 = *(const float4*)&sV[n4 + 2][tx << 2];
            float4 v3 = *(const float4*)&sV[n4 + 3][tx << 2];
            float pr[4][4] = {{p0.x,p0.y,p0.z,p0.w},{p1.x,p1.y,p1.z,p1.w},
                              {p2.x,p2.y,p2.z,p2.w},{p3.x,p3.y,p3.z,p3.w}};
            float vr[4][4] = {{v0.x,v0.y,v0.z,v0.w},{v1.x,v1.y,v1.z,v1.w},
                              {v2.x,v2.y,v2.z,v2.w},{v3.x,v3.y,v3.z,v3.w}};
#pragma unroll
            for (int i = 0; i < 4; i++)
#pragma unroll
                for (int j = 0; j < 4; j++) {
                    float acc = Oa[i][j];
#pragma unroll
                    for (int n = 0; n < 4; n++)
                        acc = fmaf(pr[i][n], vr[n][j], acc);
                    Oa[i][j] = acc;
                }
        }
        __syncthreads();
    }

    // normalize + write [b,l,h*hd]
#pragma unroll
    for (int i = 0; i < 4; i++) {
        int row = q0 + (ty << 2) + i;
        float inv = 1.f / l_i[i];
        float4 o = make_float4(Oa[i][0] * inv, Oa[i][1] * inv,
                               Oa[i][2] * inv, Oa[i][3] * inv);
        *(float4*)&g_attn[(size_t)(b * L_ + row) * D_ + h * HD_ + (tx << 2)] = o;
    }
}

// ---------------- launch ----------------------------------------------------
extern "C" void kernel_launch(void* const* d_in, const int* in_sizes, int n_in,
                              void* d_out, int out_size)
{
    const float* q_in = (const float*)d_in[0];
    const float* k_in = (const float*)d_in[1];
    // d_in[2] = v_in (unused by reference), d_in[3] = mask (tril, hardcoded causal)
    const float* rope = (const float*)d_in[4];
    const float* Wq   = (const float*)d_in[5];
    const float* bq   = (const float*)d_in[6];
    const float* Wkv  = (const float*)d_in[7];
    const float* bkv  = (const float*)d_in[8];
    const float* Wp   = (const float*)d_in[9];
    const float* bp   = (const float*)d_in[10];
    float* out = (float*)d_out;

    float *qp, *kvp, *attn;
    cudaGetSymbolAddress((void**)&qp,   g_qp);
    cudaGetSymbolAddress((void**)&kvp,  g_kvp);
    cudaGetSymbolAddress((void**)&attn, g_attn);

    // 1) Q projection: [8192,1024] = q_in @ Wq + bq
    sgemm_bias_kernel<<<dim3(D_ / 128, BL_ / 128), 256>>>(q_in, Wq, bq, qp, BL_, D_, D_);
    // 2) KV projection: [8192,2048] = k_in @ Wkv + bkv
    sgemm_bias_kernel<<<dim3(2 * D_ / 128, BL_ / 128), 256>>>(k_in, Wkv, bkv, kvp, BL_, 2 * D_, D_);
    // 3) RoPE + split + transpose to [b,h,l,hd]
    rope_split_kernel<<<(B_ * H_ * L_ * 32) / 256, 256>>>(rope);
    // 4) causal flash attention
    cudaFuncSetAttribute(flash_kernel, cudaFuncAttributeMaxDynamicSharedMemorySize, FLASH_SMEM);
    flash_kernel<<<dim3(L_ / FBM, BH_), 256, FLASH_SMEM>>>();
    // 5) output projection: out = attn @ Wp + bp
    sgemm_bias_kernel<<<dim3(D_ / 128, BL_ / 128), 256>>>(attn, Wp, bp, out, BL_, D_, D_);
}

// round 11
// speedup vs baseline: 1.0052x; 1.0033x over previous
#include <cuda_runtime.h>
#include <math.h>

// Problem constants
#define B_   4
#define L_   2048
#define D_   1024
#define H_   16
#define HD_  64
#define BH_  (B_*H_)
#define BL_  (B_*L_)
#define SCALE_ 0.125f   // 1/sqrt(64)

// ---------------- scratch (device globals; no allocation allowed) ----------
__device__ float g_qp [BL_ * D_];          // q projection  [b*l][1024]
__device__ float g_kvp[BL_ * 2 * D_];      // kv projection [b*l][2048]
__device__ float g_q  [BH_ * L_ * HD_];    // [b,h,l,hd] after rope
__device__ float g_k  [BH_ * L_ * HD_];
__device__ float g_v  [BH_ * L_ * HD_];
__device__ float g_attn[BL_ * D_];         // [b,l,h*hd]

// ---------------- fp32 SGEMM: C[M,N] = A[M,K] @ W[K,N] + bias --------------
// 128x128 tile, BK=8, 256 threads, 8x8 per thread.
__global__ void __launch_bounds__(256) sgemm_bias_kernel(
    const float* __restrict__ A, const float* __restrict__ W,
    const float* __restrict__ bias, float* __restrict__ C,
    int M, int N, int K)
{
    __shared__ float As[8][128];
    __shared__ float Bs[8][128];
    const int tid = threadIdx.x;
    const int tx = tid & 15, ty = tid >> 4;
    const int m0 = blockIdx.y << 7, n0 = blockIdx.x << 7;

    const int arow = tid >> 1;          // 0..127
    const int acol = (tid & 1) << 2;    // 0 or 4
    const int brow = tid >> 5;          // 0..7
    const int bcol = (tid & 31) << 2;   // 0..124

    const float* Ap = A + (size_t)(m0 + arow) * K + acol;
    const float* Wp = W + (size_t)brow * N + n0 + bcol;

    float acc[8][8];
#pragma unroll
    for (int i = 0; i < 8; i++)
#pragma unroll
        for (int j = 0; j < 8; j++) acc[i][j] = 0.f;

    for (int kt = 0; kt < K; kt += 8) {
        float4 av = *(const float4*)(Ap + kt);
        float4 bv = *(const float4*)(Wp + (size_t)kt * N);
        As[acol + 0][arow] = av.x;
        As[acol + 1][arow] = av.y;
        As[acol + 2][arow] = av.z;
        As[acol + 3][arow] = av.w;
        *(float4*)&Bs[brow][bcol] = bv;
        __syncthreads();
#pragma unroll
        for (int k = 0; k < 8; k++) {
            float4 a0 = *(const float4*)&As[k][ty << 3];
            float4 a1 = *(const float4*)&As[k][(ty << 3) + 4];
            float4 b0 = *(const float4*)&Bs[k][tx << 3];
            float4 b1 = *(const float4*)&Bs[k][(tx << 3) + 4];
            float a[8]  = {a0.x, a0.y, a0.z, a0.w, a1.x, a1.y, a1.z, a1.w};
            float bb[8] = {b0.x, b0.y, b0.z, b0.w, b1.x, b1.y, b1.z, b1.w};
#pragma unroll
            for (int i = 0; i < 8; i++)
#pragma unroll
                for (int j = 0; j < 8; j++)
                    acc[i][j] = fmaf(a[i], bb[j], acc[i][j]);
        }
        __syncthreads();
    }

    float bj[8];
#pragma unroll
    for (int j = 0; j < 8; j++) bj[j] = bias[n0 + (tx << 3) + j];
#pragma unroll
    for (int i = 0; i < 8; i++) {
        size_t row = (size_t)(m0 + (ty << 3) + i);
        float* Cp = C + row * N + n0 + (tx << 3);
        float4 o0 = make_float4(acc[i][0] + bj[0], acc[i][1] + bj[1],
                                acc[i][2] + bj[2], acc[i][3] + bj[3]);
        float4 o1 = make_float4(acc[i][4] + bj[4], acc[i][5] + bj[5],
                                acc[i][6] + bj[6], acc[i][7] + bj[7]);
        *(float4*)(Cp)     = o0;
        *(float4*)(Cp + 4) = o1;
    }
}

// ---------------- RoPE + head split/transpose ------------------------------
// One thread per (b,h,l,pair). rope[l, 2i] = sin, rope[l, 2i+1] = cos.
// Writes g_q/g_k/g_v in [b,h,l,hd] layout.
__global__ void __launch_bounds__(256) rope_split_kernel(const float* __restrict__ rope)
{
    int t = blockIdx.x * 256 + threadIdx.x;   // 0 .. B*H*L*32-1
    int i = t & 31;
    int l = (t >> 5) & (L_ - 1);
    int h = (t >> 16) & (H_ - 1);
    int b = t >> 20;

    float2 rp = ((const float2*)rope)[l * 32 + i];
    float sn = rp.x, cs = rp.y;

    const float2* qp2 = (const float2*)g_qp;
    const float2* kv2 = (const float2*)g_kvp;
    float2 q = qp2[(size_t)(b * L_ + l) * 512 + h * 32 + i];
    size_t kvbase = (size_t)(b * L_ + l) * 1024;
    float2 k = kv2[kvbase + h * 32 + i];
    float2 v = kv2[kvbase + 512 + h * 32 + i];

    float2 qo, ko;
    qo.x = q.x * cs - q.y * sn;  qo.y = q.x * sn + q.y * cs;
    ko.x = k.x * cs - k.y * sn;  ko.y = k.x * sn + k.y * cs;

    size_t o = (size_t)((b * H_ + h) * L_ + l) * 32 + i;
    ((float2*)g_q)[o] = qo;
    ((float2*)g_k)[o] = ko;
    ((float2*)g_v)[o] = v;
}

// ---------------- causal flash attention (fp32 SIMT) -----------------------
// BM=BN=64, HD=64. 256 threads = 16x16, 4x4 outputs/thread.
#define FBM 64
#define FBN 64
#define FPAD 68
#define FLASH_SMEM ((64*FPAD /*Qt*/ + 64*FPAD /*Kt*/ + FBN*64 /*V*/ + FBM*FPAD /*P*/) * 4)

__global__ void __launch_bounds__(256) flash_kernel()
{
    extern __shared__ float sm[];
    float (*sQt)[FPAD] = (float(*)[FPAD])sm;                       // [hd][row]
    float (*sKt)[FPAD] = (float(*)[FPAD])(sm + 64 * FPAD);         // [hd][col]
    float (*sV)[64]    = (float(*)[64])  (sm + 2 * 64 * FPAD);     // [n][hd]
    float (*sP)[FPAD]  = (float(*)[FPAD])(sm + 2 * 64 * FPAD + FBN * 64);

    const int tid = threadIdx.x;
    const int tx = tid & 15, ty = tid >> 4;
    const int qb = blockIdx.x;            // query block (32)
    const int bh = blockIdx.y;            // 0..63
    const int q0 = qb * FBM;
    const int b = bh >> 4, h = bh & 15;

    const float* Qb = g_q + ((size_t)bh * L_ + q0) * HD_;
    const float* Kb = g_k + (size_t)bh * L_ * HD_;
    const float* Vb = g_v + (size_t)bh * L_ * HD_;

    // Q tile -> transposed smem (once per block)
#pragma unroll
    for (int u = 0; u < 4; u++) {
        int idx = tid + 256 * u;
        int r = idx >> 4;
        int c = (idx & 15) << 2;
        float4 qv = *(const float4*)(Qb + (size_t)r * HD_ + c);
        sQt[c + 0][r] = qv.x; sQt[c + 1][r] = qv.y;
        sQt[c + 2][r] = qv.z; sQt[c + 3][r] = qv.w;
    }

    float m_i[4], l_i[4], Oa[4][4];
#pragma unroll
    for (int i = 0; i < 4; i++) {
        m_i[i] = -INFINITY; l_i[i] = 0.f;
#pragma unroll
        for (int j = 0; j < 4; j++) Oa[i][j] = 0.f;
    }

    for (int kb = 0; kb <= qb; kb++) {
        const int n0 = kb * FBN;
        // K tile transposed + V tile natural
#pragma unroll
        for (int u = 0; u < 4; u++) {
            int idx = tid + 256 * u;
            int r = idx >> 4;
            int c = (idx & 15) << 2;
            float4 kv = *(const float4*)(Kb + (size_t)(n0 + r) * HD_ + c);
            sKt[c + 0][r] = kv.x; sKt[c + 1][r] = kv.y;
            sKt[c + 2][r] = kv.z; sKt[c + 3][r] = kv.w;
            float4 vv = *(const float4*)(Vb + (size_t)(n0 + r) * HD_ + c);
            *(float4*)&sV[r][c] = vv;
        }
        __syncthreads();

        // S = Q K^T (4x4 per thread)
        float S[4][4];
#pragma unroll
        for (int i = 0; i < 4; i++)
#pragma unroll
            for (int j = 0; j < 4; j++) S[i][j] = 0.f;

#pragma unroll 8
        for (int kk = 0; kk < HD_; kk++) {
            float4 a  = *(const float4*)&sQt[kk][ty << 2];
            float4 bb = *(const float4*)&sKt[kk][tx << 2];
            float av[4] = {a.x, a.y, a.z, a.w};
            float bv[4] = {bb.x, bb.y, bb.z, bb.w};
#pragma unroll
            for (int i = 0; i < 4; i++)
#pragma unroll
                for (int j = 0; j < 4; j++)
                    S[i][j] = fmaf(av[i], bv[j], S[i][j]);
        }

        const bool diag = (kb == qb);
#pragma unroll
        for (int i = 0; i < 4; i++) {
            int row = q0 + (ty << 2) + i;
#pragma unroll
            for (int j = 0; j < 4; j++) {
                float s = S[i][j] * SCALE_;
                if (diag && (n0 + (tx << 2) + j > row)) s = -1e9f;
                S[i][j] = s;
            }
        }

        // online softmax; rows are shared by the 16 tx-lanes (shuffle width 16)
#pragma unroll
        for (int i = 0; i < 4; i++) {
            float rm = fmaxf(fmaxf(S[i][0], S[i][1]), fmaxf(S[i][2], S[i][3]));
#pragma unroll
            for (int off = 8; off >= 1; off >>= 1)
                rm = fmaxf(rm, __shfl_xor_sync(0xffffffffu, rm, off, 16));
            float mn = fmaxf(m_i[i], rm);
            float corr = __expf(m_i[i] - mn);
            float ps = 0.f;
#pragma unroll
            for (int j = 0; j < 4; j++) {
                float p = __expf(S[i][j] - mn);
                S[i][j] = p;
                ps += p;
            }
#pragma unroll
            for (int off = 8; off >= 1; off >>= 1)
                ps += __shfl_xor_sync(0xffffffffu, ps, off, 16);
            l_i[i] = l_i[i] * corr + ps;
            m_i[i] = mn;
#pragma unroll
            for (int j = 0; j < 4; j++) Oa[i][j] *= corr;
            *(float4*)&sP[(ty << 2) + i][tx << 2] =
                make_float4(S[i][0], S[i][1], S[i][2], S[i][3]);
        }
        __syncthreads();

        // O += P @ V
#pragma unroll 4
        for (int n4 = 0; n4 < FBN; n4 += 4) {
            float4 p0 = *(const float4*)&sP[(ty << 2) + 0][n4];
            float4 p1 = *(const float4*)&sP[(ty << 2) + 1][n4];
            float4 p2 = *(const float4*)&sP[(ty << 2) + 2][n4];
            float4 p3 = *(const float4*)&sP[(ty << 2) + 3][n4];
            float4 v0 = *(const float4*)&sV[n4 + 0][tx << 2];
            float4 v1 = *(const float4*)&sV[n4 + 1][tx << 2];
            float4 v2 = *(const float4*)&sV[n4 + 2][tx << 2];
            float4 v3 = *(const float4*)&sV[n4 + 3][tx << 2];
            float pr[4][4] = {{p0.x,p0.y,p0.z,p0.w},{p1.x,p1.y,p1.z,p1.w},
                              {p2.x,p2.y,p2.z,p2.w},{p3.x,p3.y,p3.z,p3.w}};
            float vr[4][4] = {{v0.x,v0.y,v0.z,v0.w},{v1.x,v1.y,v1.z,v1.w},
                              {v2.x,v2.y,v2.z,v2.w},{v3.x,v3.y,v3.z,v3.w}};
#pragma unroll
            for (int i = 0; i < 4; i++)
#pragma unroll
                for (int j = 0; j < 4; j++) {
                    float acc = Oa[i][j];
#pragma unroll
                    for (int n = 0; n < 4; n++)
                        acc = fmaf(pr[i][n], vr[n][j], acc);
                    Oa[i][j] = acc;
                }
        }
        __syncthreads();
    }

    // normalize + write [b,l,h*hd]
#pragma unroll
    for (int i = 0; i < 4; i++) {
        int row = q0 + (ty << 2) + i;
        float inv = 1.f / l_i[i];
        float4 o = make_float4(Oa[i][0] * inv, Oa[i][1] * inv,
                               Oa[i][2] * inv, Oa[i][3] * inv);
        *(float4*)&g_attn[(size_t)(b * L_ + row) * D_ + h * HD_ + (tx << 2)] = o;
    }
}

// ---------------- launch ----------------------------------------------------
extern "C" void kernel_launch(void* const* d_in, const int* in_sizes, int n_in,
                              void* d_out, int out_size)
{
    const float* q_in = (const float*)d_in[0];
    const float* k_in = (const float*)d_in[1];
    // d_in[2] = v_in (unused by reference), d_in[3] = mask (tril, hardcoded causal)
    const float* rope = (const float*)d_in[4];
    const float* Wq   = (const float*)d_in[5];
    const float* bq   = (const float*)d_in[6];
    const float* Wkv  = (const float*)d_in[7];
    const float* bkv  = (const float*)d_in[8];
    const float* Wp   = (const float*)d_in[9];
    const float* bp   = (const float*)d_in[10];
    float* out = (float*)d_out;

    float *qp, *kvp, *attn;
    cudaGetSymbolAddress((void**)&qp,   g_qp);
    cudaGetSymbolAddress((void**)&kvp,  g_kvp);
    cudaGetSymbolAddress((void**)&attn, g_attn);

    // 1) Q projection: [8192,1024] = q_in @ Wq + bq
    sgemm_bias_kernel<<<dim3(D_ / 128, BL_ / 128), 256>>>(q_in, Wq, bq, qp, BL_, D_, D_);
    // 2) KV projection: [8192,2048] = k_in @ Wkv + bkv
    sgemm_bias_kernel<<<dim3(2 * D_ / 128, BL_ / 128), 256>>>(k_in, Wkv, bkv, kvp, BL_, 2 * D_, D_);
    // 3) RoPE + split + transpose to [b,h,l,hd]
    rope_split_kernel<<<(B_ * H_ * L_ * 32) / 256, 256>>>(rope);
    // 4) causal flash attention
    cudaFuncSetAttribute(flash_kernel, cudaFuncAttributeMaxDynamicSharedMemorySize, FLASH_SMEM);
    flash_kernel<<<dim3(L_ / FBM, BH_), 256, FLASH_SMEM>>>();
    // 5) output projection: out = attn @ Wp + bp
    sgemm_bias_kernel<<<dim3(D_ / 128, BL_ / 128), 256>>>(attn, Wp, bp, out, BL_, D_, D_);
}

// round 12
// speedup vs baseline: 2.7778x; 2.7633x over previous
#include <cuda_runtime.h>
#include <math.h>
#include <stdint.h>

// Problem constants
#define B_   4
#define L_   2048
#define D_   1024
#define H_   16
#define HD_  64
#define BH_  (B_*H_)
#define BL_  (B_*L_)
#define SCALE_ 0.125f   // 1/sqrt(64)

// ---------------- scratch (device globals; no allocation allowed) ----------
__device__ float g_qp [BL_ * D_];          // q projection  [b*l][1024]
__device__ float g_kvp[BL_ * 2 * D_];      // kv projection [b*l][2048]
__device__ float g_q  [BH_ * L_ * HD_];    // [b,h,l,hd] after rope
__device__ float g_k  [BH_ * L_ * HD_];
__device__ float g_v  [BH_ * L_ * HD_];
__device__ float g_attn[BL_ * D_];         // [b,l,h*hd]

// ---------------- tf32 helpers ---------------------------------------------
__device__ __forceinline__ uint32_t f2tf(float f) {
    uint32_t r;
    asm("cvt.rna.tf32.f32 %0, %1;" : "=r"(r) : "f"(f));
    return r;
}

__device__ __forceinline__ void mma_tf32(float* d, const uint32_t* a, const uint32_t* b) {
    asm volatile(
        "mma.sync.aligned.m16n8k8.row.col.f32.tf32.tf32.f32 "
        "{%0,%1,%2,%3}, {%4,%5,%6,%7}, {%8,%9}, {%0,%1,%2,%3};"
        : "+f"(d[0]), "+f"(d[1]), "+f"(d[2]), "+f"(d[3])
        : "r"(a[0]), "r"(a[1]), "r"(a[2]), "r"(a[3]), "r"(b[0]), "r"(b[1]));
}

// ---------------- TF32 GEMM: C[M,N] = A[M,K] @ W[K,N] + bias ---------------
// 128x128 block, BK=16, 256 threads (8 warps, 2x4 grid, 64x32 warp tile).
#define GAS 20    // sA stride (floats): conflict-free fragment reads
#define GBS 136   // sB stride (floats): conflict-free fragment reads

__global__ void __launch_bounds__(256) gemm_tf32_kernel(
    const float* __restrict__ A, const float* __restrict__ W,
    const float* __restrict__ bias, float* __restrict__ C,
    int M, int N, int K)
{
    __shared__ uint32_t sA[128 * GAS];   // [m][k] tf32
    __shared__ uint32_t sB[16 * GBS];    // [k][n] tf32

    const int tid = threadIdx.x;
    const int lane = tid & 31;
    const int wid = tid >> 5;
    const int g = lane >> 2, t = lane & 3;
    const int m0 = blockIdx.y << 7, n0 = blockIdx.x << 7;
    const int wm = (wid & 1) << 6;    // 0 or 64
    const int wn = (wid >> 1) << 5;   // 0,32,64,96

    float acc[4][4][4];
#pragma unroll
    for (int i = 0; i < 4; i++)
#pragma unroll
        for (int j = 0; j < 4; j++)
#pragma unroll
            for (int e = 0; e < 4; e++) acc[i][j][e] = 0.f;

    // loader addressing (coalesced gmem reads)
    const int ar = tid >> 2;             // 0..63 (A rows, +64 for part1)
    const int ac4 = (tid & 3) << 2;      // 0,4,8,12
    const int bk = tid >> 5;             // 0..7 (+8 for part1)
    const int bc4 = (tid & 31) << 2;     // 0..124
    const float* Ap0 = A + (size_t)(m0 + ar) * K + ac4;
    const float* Ap1 = Ap0 + (size_t)64 * K;
    const float* Wp0 = W + (size_t)bk * N + n0 + bc4;
    const float* Wp1 = Wp0 + (size_t)8 * N;

    float4 ra0 = *(const float4*)(Ap0);
    float4 ra1 = *(const float4*)(Ap1);
    float4 rb0 = *(const float4*)(Wp0);
    float4 rb1 = *(const float4*)(Wp1);

    for (int kt = 0; kt < K; kt += 16) {
        // stage to smem (tf32)
        sA[ar * GAS + ac4 + 0] = f2tf(ra0.x);
        sA[ar * GAS + ac4 + 1] = f2tf(ra0.y);
        sA[ar * GAS + ac4 + 2] = f2tf(ra0.z);
        sA[ar * GAS + ac4 + 3] = f2tf(ra0.w);
        sA[(ar + 64) * GAS + ac4 + 0] = f2tf(ra1.x);
        sA[(ar + 64) * GAS + ac4 + 1] = f2tf(ra1.y);
        sA[(ar + 64) * GAS + ac4 + 2] = f2tf(ra1.z);
        sA[(ar + 64) * GAS + ac4 + 3] = f2tf(ra1.w);
        {
            uint4 u0 = make_uint4(f2tf(rb0.x), f2tf(rb0.y), f2tf(rb0.z), f2tf(rb0.w));
            uint4 u1 = make_uint4(f2tf(rb1.x), f2tf(rb1.y), f2tf(rb1.z), f2tf(rb1.w));
            *(uint4*)&sB[bk * GBS + bc4] = u0;
            *(uint4*)&sB[(bk + 8) * GBS + bc4] = u1;
        }
        __syncthreads();

        if (kt + 16 < K) {
            ra0 = *(const float4*)(Ap0 + kt + 16);
            ra1 = *(const float4*)(Ap1 + kt + 16);
            rb0 = *(const float4*)(Wp0 + (size_t)(kt + 16) * N);
            rb1 = *(const float4*)(Wp1 + (size_t)(kt + 16) * N);
        }

#pragma unroll
        for (int kf = 0; kf < 2; kf++) {
            const int k0 = kf << 3;
            uint32_t af[4][4];
#pragma unroll
            for (int mf = 0; mf < 4; mf++) {
                const int r = wm + (mf << 4) + g;
                af[mf][0] = sA[r * GAS + k0 + t];
                af[mf][1] = sA[(r + 8) * GAS + k0 + t];
                af[mf][2] = sA[r * GAS + k0 + t + 4];
                af[mf][3] = sA[(r + 8) * GAS + k0 + t + 4];
            }
            uint32_t bf[4][2];
#pragma unroll
            for (int nf = 0; nf < 4; nf++) {
                const int c = wn + (nf << 3) + g;
                bf[nf][0] = sB[(k0 + t) * GBS + c];
                bf[nf][1] = sB[(k0 + t + 4) * GBS + c];
            }
#pragma unroll
            for (int mf = 0; mf < 4; mf++)
#pragma unroll
                for (int nf = 0; nf < 4; nf++)
                    mma_tf32(acc[mf][nf], af[mf], bf[nf]);
        }
        __syncthreads();
    }

    // epilogue: add bias, write float2 per acc pair
#pragma unroll
    for (int nf = 0; nf < 4; nf++) {
        const int col = n0 + wn + (nf << 3) + (t << 1);
        const float b0 = bias[col], b1 = bias[col + 1];
#pragma unroll
        for (int mf = 0; mf < 4; mf++) {
            const int row0 = m0 + wm + (mf << 4) + g;
            float2 o0 = make_float2(acc[mf][nf][0] + b0, acc[mf][nf][1] + b1);
            float2 o1 = make_float2(acc[mf][nf][2] + b0, acc[mf][nf][3] + b1);
            *(float2*)&C[(size_t)row0 * N + col] = o0;
            *(float2*)&C[(size_t)(row0 + 8) * N + col] = o1;
        }
    }
}

// ---------------- RoPE + head split/transpose ------------------------------
__global__ void __launch_bounds__(256) rope_split_kernel(const float* __restrict__ rope)
{
    int tt = blockIdx.x * 256 + threadIdx.x;   // 0 .. B*H*L*32-1
    int i = tt & 31;
    int l = (tt >> 5) & (L_ - 1);
    int h = (tt >> 16) & (H_ - 1);
    int b = tt >> 20;

    float2 rp = ((const float2*)rope)[l * 32 + i];
    float sn = rp.x, cs = rp.y;

    const float2* qp2 = (const float2*)g_qp;
    const float2* kv2 = (const float2*)g_kvp;
    float2 q = qp2[(size_t)(b * L_ + l) * 512 + h * 32 + i];
    size_t kvbase = (size_t)(b * L_ + l) * 1024;
    float2 k = kv2[kvbase + h * 32 + i];
    float2 v = kv2[kvbase + 512 + h * 32 + i];

    float2 qo, ko;
    qo.x = q.x * cs - q.y * sn;  qo.y = q.x * sn + q.y * cs;
    ko.x = k.x * cs - k.y * sn;  ko.y = k.x * sn + k.y * cs;

    size_t o = (size_t)((b * H_ + h) * L_ + l) * 32 + i;
    ((float2*)g_q)[o] = qo;
    ((float2*)g_k)[o] = ko;
    ((float2*)g_v)[o] = v;
}

// ---------------- causal flash attention (tf32 mma) ------------------------
// BM=BN=64, HD=64, 4 warps (128 threads). Each warp owns 16 query rows.
// Q fragments register-resident across the whole KV loop.
#define FS 72   // smem row stride (floats): conflict-free fragment reads
#define FSMEM (3 * 64 * FS * 4)

__global__ void __launch_bounds__(128) flash_tc_kernel()
{
    extern __shared__ uint32_t sm[];
    uint32_t* sK = sm;                  // [64][FS] tf32
    uint32_t* sV = sm + 64 * FS;        // [64][FS] tf32
    uint32_t* sP = sm + 2 * 64 * FS;    // [64][FS] tf32 (also Q fp32 staging)
    float* sPf = (float*)sP;

    const int tid = threadIdx.x;
    const int lane = tid & 31;
    const int wid = tid >> 5;          // 0..3
    const int g = lane >> 2, t = lane & 3;
    const int qb = blockIdx.x;
    const int bh = blockIdx.y;
    const int q0 = qb * 64;
    const int b = bh >> 4, h = bh & 15;
    const int mrow = wid << 4;

    const float* Qg = g_q + ((size_t)bh * L_ + q0) * HD_;
    const float* Kg = g_k + (size_t)bh * L_ * HD_;
    const float* Vg = g_v + (size_t)bh * L_ * HD_;

    // stage Q tile (fp32) into sP
#pragma unroll
    for (int u = 0; u < 8; u++) {
        int idx = tid + 128 * u;
        int r = idx >> 4;
        int c4 = (idx & 15) << 2;
        float4 q4 = *(const float4*)(Qg + (size_t)r * HD_ + c4);
        *(float4*)&sPf[r * FS + c4] = q4;
    }
    __syncthreads();

    // Q fragments (tf32), register-resident
    uint32_t qf[8][4];
#pragma unroll
    for (int kf = 0; kf < 8; kf++) {
        const int k0 = kf << 3;
        qf[kf][0] = f2tf(sPf[(mrow + g) * FS + k0 + t]);
        qf[kf][1] = f2tf(sPf[(mrow + g + 8) * FS + k0 + t]);
        qf[kf][2] = f2tf(sPf[(mrow + g) * FS + k0 + t + 4]);
        qf[kf][3] = f2tf(sPf[(mrow + g + 8) * FS + k0 + t + 4]);
    }
    // NOTE: the __syncthreads() after the first K/V tile load (below) orders
    // these LDS before any warp's P stores into sP.

    float Of[8][4];
    float m_i[2] = {-INFINITY, -INFINITY};
    float l_i[2] = {0.f, 0.f};
#pragma unroll
    for (int nf = 0; nf < 8; nf++)
#pragma unroll
        for (int e = 0; e < 4; e++) Of[nf][e] = 0.f;

    for (int kb = 0; kb <= qb; kb++) {
        const int n0 = kb * 64;
        // cooperative K,V tile load (fp32 -> tf32 smem)
#pragma unroll
        for (int u = 0; u < 8; u++) {
            int idx = tid + 128 * u;
            int r = idx >> 4;
            int c4 = (idx & 15) << 2;
            float4 k4 = *(const float4*)(Kg + (size_t)(n0 + r) * HD_ + c4);
            float4 v4 = *(const float4*)(Vg + (size_t)(n0 + r) * HD_ + c4);
            *(uint4*)&sK[r * FS + c4] = make_uint4(f2tf(k4.x), f2tf(k4.y), f2tf(k4.z), f2tf(k4.w));
            *(uint4*)&sV[r * FS + c4] = make_uint4(f2tf(v4.x), f2tf(v4.y), f2tf(v4.z), f2tf(v4.w));
        }
        __syncthreads();

        // S = Q K^T
        float Sf[8][4];
#pragma unroll
        for (int nf = 0; nf < 8; nf++)
#pragma unroll
            for (int e = 0; e < 4; e++) Sf[nf][e] = 0.f;

#pragma unroll
        for (int nf = 0; nf < 8; nf++) {
            const int kr = (nf << 3) + g;
#pragma unroll
            for (int kf = 0; kf < 8; kf++) {
                uint32_t bfr[2];
                bfr[0] = sK[kr * FS + (kf << 3) + t];
                bfr[1] = sK[kr * FS + (kf << 3) + t + 4];
                mma_tf32(Sf[nf], qf[kf], bfr);
            }
        }

        // scale + causal mask
        const int row0 = q0 + mrow + g;
        const int row1 = row0 + 8;
        const bool diag = (kb == qb);
#pragma unroll
        for (int nf = 0; nf < 8; nf++) {
            const int c0 = n0 + (nf << 3) + (t << 1);
            const int c1 = c0 + 1;
            Sf[nf][0] *= SCALE_; Sf[nf][1] *= SCALE_;
            Sf[nf][2] *= SCALE_; Sf[nf][3] *= SCALE_;
            if (diag) {
                if (c0 > row0) Sf[nf][0] = -1e9f;
                if (c1 > row0) Sf[nf][1] = -1e9f;
                if (c0 > row1) Sf[nf][2] = -1e9f;
                if (c1 > row1) Sf[nf][3] = -1e9f;
            }
        }

        // online softmax (2 rows per lane; stats shared across the quad)
        float rm0 = -INFINITY, rm1 = -INFINITY;
#pragma unroll
        for (int nf = 0; nf < 8; nf++) {
            rm0 = fmaxf(rm0, fmaxf(Sf[nf][0], Sf[nf][1]));
            rm1 = fmaxf(rm1, fmaxf(Sf[nf][2], Sf[nf][3]));
        }
        rm0 = fmaxf(rm0, __shfl_xor_sync(0xffffffffu, rm0, 1));
        rm0 = fmaxf(rm0, __shfl_xor_sync(0xffffffffu, rm0, 2));
        rm1 = fmaxf(rm1, __shfl_xor_sync(0xffffffffu, rm1, 1));
        rm1 = fmaxf(rm1, __shfl_xor_sync(0xffffffffu, rm1, 2));

        const float mn0 = fmaxf(m_i[0], rm0);
        const float mn1 = fmaxf(m_i[1], rm1);
        const float corr0 = __expf(m_i[0] - mn0);
        const float corr1 = __expf(m_i[1] - mn1);
        m_i[0] = mn0; m_i[1] = mn1;

        float ps0 = 0.f, ps1 = 0.f;
#pragma unroll
        for (int nf = 0; nf < 8; nf++) {
            float p0 = __expf(Sf[nf][0] - mn0);
            float p1 = __expf(Sf[nf][1] - mn0);
            float p2 = __expf(Sf[nf][2] - mn1);
            float p3 = __expf(Sf[nf][3] - mn1);
            ps0 += p0 + p1;
            ps1 += p2 + p3;
            const int pc = (nf << 3) + (t << 1);
            *(uint2*)&sP[(mrow + g) * FS + pc]     = make_uint2(f2tf(p0), f2tf(p1));
            *(uint2*)&sP[(mrow + g + 8) * FS + pc] = make_uint2(f2tf(p2), f2tf(p3));
        }
        ps0 += __shfl_xor_sync(0xffffffffu, ps0, 1);
        ps0 += __shfl_xor_sync(0xffffffffu, ps0, 2);
        ps1 += __shfl_xor_sync(0xffffffffu, ps1, 1);
        ps1 += __shfl_xor_sync(0xffffffffu, ps1, 2);
        l_i[0] = l_i[0] * corr0 + ps0;
        l_i[1] = l_i[1] * corr1 + ps1;

#pragma unroll
        for (int nf = 0; nf < 8; nf++) {
            Of[nf][0] *= corr0; Of[nf][1] *= corr0;
            Of[nf][2] *= corr1; Of[nf][3] *= corr1;
        }
        __syncwarp();   // P stores visible to fragment reloads within the warp

        // O += P @ V
#pragma unroll
        for (int kf = 0; kf < 8; kf++) {
            const int k0 = kf << 3;
            uint32_t pa[4];
            pa[0] = sP[(mrow + g) * FS + k0 + t];
            pa[1] = sP[(mrow + g + 8) * FS + k0 + t];
            pa[2] = sP[(mrow + g) * FS + k0 + t + 4];
            pa[3] = sP[(mrow + g + 8) * FS + k0 + t + 4];
#pragma unroll
            for (int nf = 0; nf < 8; nf++) {
                uint32_t bfr[2];
                bfr[0] = sV[(k0 + t) * FS + (nf << 3) + g];
                bfr[1] = sV[(k0 + t + 4) * FS + (nf << 3) + g];
                mma_tf32(Of[nf], pa, bfr);
            }
        }
        __syncthreads();   // protect sK/sV/sP before next tile load
    }

    // normalize + write [b,l,h*hd]
    const float inv0 = 1.f / l_i[0];
    const float inv1 = 1.f / l_i[1];
    const int row0 = q0 + mrow + g;
    const int row1 = row0 + 8;
#pragma unroll
    for (int nf = 0; nf < 8; nf++) {
        const int col = h * HD_ + (nf << 3) + (t << 1);
        *(float2*)&g_attn[(size_t)(b * L_ + row0) * D_ + col] =
            make_float2(Of[nf][0] * inv0, Of[nf][1] * inv0);
        *(float2*)&g_attn[(size_t)(b * L_ + row1) * D_ + col] =
            make_float2(Of[nf][2] * inv1, Of[nf][3] * inv1);
    }
}

// ---------------- launch ----------------------------------------------------
extern "C" void kernel_launch(void* const* d_in, const int* in_sizes, int n_in,
                              void* d_out, int out_size)
{
    const float* q_in = (const float*)d_in[0];
    const float* k_in = (const float*)d_in[1];
    // d_in[2] = v_in (unused by reference), d_in[3] = mask (tril, hardcoded causal)
    const float* rope = (const float*)d_in[4];
    const float* Wq   = (const float*)d_in[5];
    const float* bq   = (const float*)d_in[6];
    const float* Wkv  = (const float*)d_in[7];
    const float* bkv  = (const float*)d_in[8];
    const float* Wp   = (const float*)d_in[9];
    const float* bp   = (const float*)d_in[10];
    float* out = (float*)d_out;

    float *qp, *kvp, *attn;
    cudaGetSymbolAddress((void**)&qp,   g_qp);
    cudaGetSymbolAddress((void**)&kvp,  g_kvp);
    cudaGetSymbolAddress((void**)&attn, g_attn);

    // 1) Q projection: [8192,1024] = q_in @ Wq + bq
    gemm_tf32_kernel<<<dim3(D_ / 128, BL_ / 128), 256>>>(q_in, Wq, bq, qp, BL_, D_, D_);
    // 2) KV projection: [8192,2048] = k_in @ Wkv + bkv
    gemm_tf32_kernel<<<dim3(2 * D_ / 128, BL_ / 128), 256>>>(k_in, Wkv, bkv, kvp, BL_, 2 * D_, D_);
    // 3) RoPE + split + transpose to [b,h,l,hd]
    rope_split_kernel<<<(B_ * H_ * L_ * 32) / 256, 256>>>(rope);
    // 4) causal flash attention (tf32 mma)
    cudaFuncSetAttribute(flash_tc_kernel, cudaFuncAttributeMaxDynamicSharedMemorySize, FSMEM);
    flash_tc_kernel<<<dim3(L_ / 64, BH_), 128, FSMEM>>>();
    // 5) output projection: out = attn @ Wp + bp
    gemm_tf32_kernel<<<dim3(D_ / 128, BL_ / 128), 256>>>(attn, Wp, bp, out, BL_, D_, D_);
}

// round 13
// speedup vs baseline: 3.5769x; 1.2877x over previous
#include <cuda_runtime.h>
#include <math.h>
#include <stdint.h>

// Problem constants
#define B_   4
#define L_   2048
#define D_   1024
#define H_   16
#define HD_  64
#define BH_  (B_*H_)
#define BL_  (B_*L_)
#define SCALE_ 0.125f   // 1/sqrt(64)
#define LOG2E_ 1.4426950408889634f

// ---------------- scratch (device globals; no allocation allowed) ----------
__device__ float g_qp [BL_ * D_];          // q projection  [b*l][1024]
__device__ float g_kvp[BL_ * 2 * D_];      // kv projection [b*l][2048]
__device__ float g_q  [BH_ * L_ * HD_];    // [b,h,l,hd(interleaved)] tf32 bits
__device__ float g_k  [BH_ * L_ * HD_];    // [b,h,l,hd(interleaved)] tf32 bits
__device__ float g_vt [BH_ * HD_ * L_];    // [b,h,hd,l] transposed, tf32 bits
__device__ float g_attn[BL_ * D_];         // [b,l,h*hd]

// ---------------- tf32 helpers ---------------------------------------------
__device__ __forceinline__ uint32_t f2tf(float f) {
    uint32_t r;
    asm("cvt.rna.tf32.f32 %0, %1;" : "=r"(r) : "f"(f));
    return r;
}
__device__ __forceinline__ float f2tf_f(float f) {
    uint32_t r = f2tf(f);
    return __uint_as_float(r);
}
__device__ __forceinline__ float ex2(float x) {
    float r;
    asm("ex2.approx.f32 %0, %1;" : "=f"(r) : "f"(x));
    return r;
}

__device__ __forceinline__ void mma_tf32(float* d, const uint32_t* a, const uint32_t* b) {
    asm volatile(
        "mma.sync.aligned.m16n8k8.row.col.f32.tf32.tf32.f32 "
        "{%0,%1,%2,%3}, {%4,%5,%6,%7}, {%8,%9}, {%0,%1,%2,%3};"
        : "+f"(d[0]), "+f"(d[1]), "+f"(d[2]), "+f"(d[3])
        : "r"(a[0]), "r"(a[1]), "r"(a[2]), "r"(a[3]), "r"(b[0]), "r"(b[1]));
}

// cp.async 16B (L2-resident data; bypass L1 with .cg)
__device__ __forceinline__ void cp16(uint32_t smem_addr, const void* gptr) {
    asm volatile("cp.async.cg.shared.global [%0], [%1], 16;" :: "r"(smem_addr), "l"(gptr));
}
#define CP_COMMIT() asm volatile("cp.async.commit_group;")
#define CP_WAIT0()  asm volatile("cp.async.wait_group 0;")

// within-8 hd interleave: logical w -> phys ((w&3)<<1) | (w>>2)
__device__ __forceinline__ int ilv(int j) {
    int w = j & 7;
    return (j & 56) | (((w & 3) << 1) | (w >> 2));
}

// ---------------- TF32 GEMM: C[M,N] = A[M,K] @ W[K,N] + bias ---------------
// 128x128 block, BK=16, 256 threads (8 warps, 2x4 grid, 64x32 warp tile).
// Double-buffered smem, one barrier per k-tile.
#define GAS 20    // sA stride (floats)
#define GBS 136   // sB stride (floats)

__global__ void __launch_bounds__(256) gemm_tf32_kernel(
    const float* __restrict__ A, const float* __restrict__ W,
    const float* __restrict__ bias, float* __restrict__ C,
    int M, int N, int K)
{
    __shared__ uint32_t sA[2][128 * GAS];
    __shared__ uint32_t sB[2][16 * GBS];

    const int tid = threadIdx.x;
    const int lane = tid & 31;
    const int wid = tid >> 5;
    const int g = lane >> 2, t = lane & 3;
    const int m0 = blockIdx.y << 7, n0 = blockIdx.x << 7;
    const int wm = (wid & 1) << 6;
    const int wn = (wid >> 1) << 5;

    float acc[4][4][4];
#pragma unroll
    for (int i = 0; i < 4; i++)
#pragma unroll
        for (int j = 0; j < 4; j++)
#pragma unroll
            for (int e = 0; e < 4; e++) acc[i][j][e] = 0.f;

    const int ar = tid >> 2;
    const int ac4 = (tid & 3) << 2;
    const int bk = tid >> 5;
    const int bc4 = (tid & 31) << 2;
    const float* Ap0 = A + (size_t)(m0 + ar) * K + ac4;
    const float* Ap1 = Ap0 + (size_t)64 * K;
    const float* Wp0 = W + (size_t)bk * N + n0 + bc4;
    const float* Wp1 = Wp0 + (size_t)8 * N;

    // prologue: tile 0 -> buf 0
    {
        float4 ra0 = *(const float4*)(Ap0);
        float4 ra1 = *(const float4*)(Ap1);
        float4 rb0 = *(const float4*)(Wp0);
        float4 rb1 = *(const float4*)(Wp1);
        uint32_t* a = sA[0]; uint32_t* b = sB[0];
        a[ar * GAS + ac4 + 0] = f2tf(ra0.x); a[ar * GAS + ac4 + 1] = f2tf(ra0.y);
        a[ar * GAS + ac4 + 2] = f2tf(ra0.z); a[ar * GAS + ac4 + 3] = f2tf(ra0.w);
        a[(ar+64) * GAS + ac4 + 0] = f2tf(ra1.x); a[(ar+64) * GAS + ac4 + 1] = f2tf(ra1.y);
        a[(ar+64) * GAS + ac4 + 2] = f2tf(ra1.z); a[(ar+64) * GAS + ac4 + 3] = f2tf(ra1.w);
        *(uint4*)&b[bk * GBS + bc4] = make_uint4(f2tf(rb0.x), f2tf(rb0.y), f2tf(rb0.z), f2tf(rb0.w));
        *(uint4*)&b[(bk+8) * GBS + bc4] = make_uint4(f2tf(rb1.x), f2tf(rb1.y), f2tf(rb1.z), f2tf(rb1.w));
    }
    __syncthreads();

    int cur = 0;
    for (int kt = 0; kt < K; kt += 16) {
        const bool has_next = (kt + 16 < K);
        float4 ra0, ra1, rb0, rb1;
        if (has_next) {
            ra0 = *(const float4*)(Ap0 + kt + 16);
            ra1 = *(const float4*)(Ap1 + kt + 16);
            rb0 = *(const float4*)(Wp0 + (size_t)(kt + 16) * N);
            rb1 = *(const float4*)(Wp1 + (size_t)(kt + 16) * N);
        }

        const uint32_t* a_ = sA[cur];
        const uint32_t* b_ = sB[cur];
#pragma unroll
        for (int kf = 0; kf < 2; kf++) {
            const int k0 = kf << 3;
            uint32_t af[4][4];
#pragma unroll
            for (int mf = 0; mf < 4; mf++) {
                const int r = wm + (mf << 4) + g;
                af[mf][0] = a_[r * GAS + k0 + t];
                af[mf][1] = a_[(r + 8) * GAS + k0 + t];
                af[mf][2] = a_[r * GAS + k0 + t + 4];
                af[mf][3] = a_[(r + 8) * GAS + k0 + t + 4];
            }
            uint32_t bf[4][2];
#pragma unroll
            for (int nf = 0; nf < 4; nf++) {
                const int c = wn + (nf << 3) + g;
                bf[nf][0] = b_[(k0 + t) * GBS + c];
                bf[nf][1] = b_[(k0 + t + 4) * GBS + c];
            }
#pragma unroll
            for (int mf = 0; mf < 4; mf++)
#pragma unroll
                for (int nf = 0; nf < 4; nf++)
                    mma_tf32(acc[mf][nf], af[mf], bf[nf]);
        }

        if (has_next) {
            uint32_t* a = sA[cur ^ 1]; uint32_t* b = sB[cur ^ 1];
            a[ar * GAS + ac4 + 0] = f2tf(ra0.x); a[ar * GAS + ac4 + 1] = f2tf(ra0.y);
            a[ar * GAS + ac4 + 2] = f2tf(ra0.z); a[ar * GAS + ac4 + 3] = f2tf(ra0.w);
            a[(ar+64) * GAS + ac4 + 0] = f2tf(ra1.x); a[(ar+64) * GAS + ac4 + 1] = f2tf(ra1.y);
            a[(ar+64) * GAS + ac4 + 2] = f2tf(ra1.z); a[(ar+64) * GAS + ac4 + 3] = f2tf(ra1.w);
            *(uint4*)&b[bk * GBS + bc4] = make_uint4(f2tf(rb0.x), f2tf(rb0.y), f2tf(rb0.z), f2tf(rb0.w));
            *(uint4*)&b[(bk+8) * GBS + bc4] = make_uint4(f2tf(rb1.x), f2tf(rb1.y), f2tf(rb1.z), f2tf(rb1.w));
        }
        __syncthreads();
        cur ^= 1;
    }

    // epilogue
#pragma unroll
    for (int nf = 0; nf < 4; nf++) {
        const int col = n0 + wn + (nf << 3) + (t << 1);
        const float b0 = bias[col], b1 = bias[col + 1];
#pragma unroll
        for (int mf = 0; mf < 4; mf++) {
            const int row0 = m0 + wm + (mf << 4) + g;
            *(float2*)&C[(size_t)row0 * N + col] =
                make_float2(acc[mf][nf][0] + b0, acc[mf][nf][1] + b1);
            *(float2*)&C[(size_t)(row0 + 8) * N + col] =
                make_float2(acc[mf][nf][2] + b0, acc[mf][nf][3] + b1);
        }
    }
}

// ---------------- RoPE + head split + V transpose (all outputs tf32) -------
// grid (L/64, BH), 256 threads. Block: 64 rows x 64 hd for one head.
__global__ void __launch_bounds__(256) rope_split_kernel(const float* __restrict__ rope)
{
    __shared__ float sv[64][65];

    const int tid = threadIdx.x;
    const int l0 = blockIdx.x << 6;
    const int bh = blockIdx.y;
    const int b = bh >> 4, h = bh & 15;

    const int p = tid & 31;        // hd pair index
    const int lr = (tid >> 5) << 3;  // l base (8 per thread)

    const int j0 = ilv(2 * p);
    const int j1 = ilv(2 * p + 1);

#pragma unroll
    for (int u = 0; u < 8; u++) {
        const int l = lr + u;
        float2 rp = ((const float2*)rope)[(l0 + l) * 32 + p];
        const float sn = rp.x, cs = rp.y;

        const size_t rowq = (size_t)(b * L_ + l0 + l);
        float2 q = ((const float2*)g_qp)[rowq * 512 + h * 32 + p];
        const size_t kvb = rowq * 1024;
        float2 k = ((const float2*)g_kvp)[kvb + h * 32 + p];
        float2 v = ((const float2*)g_kvp)[kvb + 512 + h * 32 + p];

        float qe = q.x * cs - q.y * sn, qo = q.x * sn + q.y * cs;
        float ke = k.x * cs - k.y * sn, ko = k.x * sn + k.y * cs;

        const size_t ob = (size_t)(bh * L_ + l0 + l) * 64;
        g_q[ob + j0] = f2tf_f(qe);
        g_q[ob + j1] = f2tf_f(qo);
        g_k[ob + j0] = f2tf_f(ke);
        g_k[ob + j1] = f2tf_f(ko);

        sv[l][2 * p]     = v.x;
        sv[l][2 * p + 1] = v.y;
    }
    __syncthreads();

    // transposed V write: g_vt[bh][hd][l]
    const int hd = tid >> 2;
    const int c0 = (tid & 3) << 4;
    float* dst = g_vt + ((size_t)bh * 64 + hd) * L_ + l0 + c0;
#pragma unroll
    for (int j4 = 0; j4 < 4; j4++) {
        float4 o;
        o.x = f2tf_f(sv[c0 + j4 * 4 + 0][hd]);
        o.y = f2tf_f(sv[c0 + j4 * 4 + 1][hd]);
        o.z = f2tf_f(sv[c0 + j4 * 4 + 2][hd]);
        o.w = f2tf_f(sv[c0 + j4 * 4 + 3][hd]);
        *(float4*)(dst + j4 * 4) = o;
    }
}

// ---------------- causal flash attention (tf32 mma, cp.async pipelined) ----
// BM=BN=64, HD=64, 4 warps. P register-resident; V fragments LDS.64.
#define FS 72
#define FTILE (64 * FS)               // words per K or V tile
#define FSMEM (4 * FTILE * 4)         // 2 buffers x (K+V)

__global__ void __launch_bounds__(128) flash_tc_kernel()
{
    extern __shared__ float smf[];
    float* bufK[2] = { smf,             smf + 2 * FTILE };
    float* bufV[2] = { smf + FTILE,     smf + 3 * FTILE };

    const int tid = threadIdx.x;
    const int lane = tid & 31;
    const int wid = tid >> 5;
    const int g = lane >> 2, t = lane & 3;
    const int bh = blockIdx.x;
    const int qb = 31 - blockIdx.y;     // heavy blocks first
    const int q0 = qb * 64;
    const int b = bh >> 4, h = bh & 15;
    const int mrow = wid << 4;

    const float* Qg = g_q + ((size_t)bh * L_ + q0) * HD_;
    const float* Kg = g_k + (size_t)bh * L_ * HD_;
    const float* Vt = g_vt + (size_t)bh * HD_ * L_;

    const int cr = tid >> 4;            // cp rows 0..7 (+8 per u)
    const int cc4 = (tid & 15) << 2;

    // issue tile 0 -> buf 0
    {
        uint32_t skb = (uint32_t)__cvta_generic_to_shared(bufK[0]);
        uint32_t svb = (uint32_t)__cvta_generic_to_shared(bufV[0]);
#pragma unroll
        for (int u = 0; u < 8; u++) {
            int r = cr + (u << 3);
            cp16(skb + (uint32_t)(r * FS + cc4) * 4, Kg + (size_t)r * 64 + cc4);
            cp16(svb + (uint32_t)(r * FS + cc4) * 4, Vt + (size_t)r * L_ + cc4);
        }
        CP_COMMIT();
    }

    // stage Q (already tf32 bits, hd-interleaved) into buf1 K region
#pragma unroll
    for (int u = 0; u < 8; u++) {
        int idx = tid + (u << 7);
        int r = idx >> 4;
        int c4 = (idx & 15) << 2;
        *(float4*)&bufK[1][r * FS + c4] = *(const float4*)(Qg + (size_t)r * 64 + c4);
    }
    __syncthreads();

    // Q fragments: LDS.64 pairs (a0,a2) and (a1,a3)
    uint32_t qf[8][4];
#pragma unroll
    for (int kf = 0; kf < 8; kf++) {
        uint2 p0 = *(const uint2*)&bufK[1][(mrow + g) * FS + (kf << 3) + 2 * t];
        uint2 p1 = *(const uint2*)&bufK[1][(mrow + g + 8) * FS + (kf << 3) + 2 * t];
        qf[kf][0] = p0.x; qf[kf][1] = p1.x; qf[kf][2] = p0.y; qf[kf][3] = p1.y;
    }

    float Of[8][4];
    float m_i[2] = {-INFINITY, -INFINITY};
    float l_i[2] = {0.f, 0.f};
#pragma unroll
    for (int nf = 0; nf < 8; nf++)
#pragma unroll
        for (int e = 0; e < 4; e++) Of[nf][e] = 0.f;

    const float SC2 = SCALE_ * LOG2E_;
    int cur = 0;

    for (int kb = 0; kb <= qb; kb++) {
        CP_WAIT0();
        __syncthreads();

        // prefetch next tile into other buffer (overlaps with compute)
        if (kb < qb) {
            const int nn = (kb + 1) * 64;
            uint32_t skb = (uint32_t)__cvta_generic_to_shared(bufK[cur ^ 1]);
            uint32_t svb = (uint32_t)__cvta_generic_to_shared(bufV[cur ^ 1]);
#pragma unroll
            for (int u = 0; u < 8; u++) {
                int r = cr + (u << 3);
                cp16(skb + (uint32_t)(r * FS + cc4) * 4, Kg + (size_t)(nn + r) * 64 + cc4);
                cp16(svb + (uint32_t)(r * FS + cc4) * 4, Vt + (size_t)r * L_ + nn + cc4);
            }
            CP_COMMIT();
        }

        const uint32_t* sK = (const uint32_t*)bufK[cur];
        const uint32_t* sV = (const uint32_t*)bufV[cur];
        const int n0 = kb * 64;

        // S = Q K^T
        float Sf[8][4];
#pragma unroll
        for (int nf = 0; nf < 8; nf++) {
#pragma unroll
            for (int e = 0; e < 4; e++) Sf[nf][e] = 0.f;
            const uint32_t* krow = sK + ((nf << 3) + g) * FS + 2 * t;
#pragma unroll
            for (int kf = 0; kf < 8; kf++) {
                uint2 bv = *(const uint2*)(krow + (kf << 3));
                uint32_t bfr[2] = { bv.x, bv.y };
                mma_tf32(Sf[nf], qf[kf], bfr);
            }
        }

        // scale (log2 domain) + causal mask
        const int row0 = q0 + mrow + g;
        const int row1 = row0 + 8;
        const bool diag = (kb == qb);
#pragma unroll
        for (int nf = 0; nf < 8; nf++) {
            Sf[nf][0] *= SC2; Sf[nf][1] *= SC2;
            Sf[nf][2] *= SC2; Sf[nf][3] *= SC2;
            if (diag) {
                const int c0 = n0 + (nf << 3) + 2 * t;
                if (c0 > row0)     Sf[nf][0] = -1e9f;
                if (c0 + 1 > row0) Sf[nf][1] = -1e9f;
                if (c0 > row1)     Sf[nf][2] = -1e9f;
                if (c0 + 1 > row1) Sf[nf][3] = -1e9f;
            }
        }

        // online softmax (base-2)
        float rm0 = -INFINITY, rm1 = -INFINITY;
#pragma unroll
        for (int nf = 0; nf < 8; nf++) {
            rm0 = fmaxf(rm0, fmaxf(Sf[nf][0], Sf[nf][1]));
            rm1 = fmaxf(rm1, fmaxf(Sf[nf][2], Sf[nf][3]));
        }
        rm0 = fmaxf(rm0, __shfl_xor_sync(0xffffffffu, rm0, 1));
        rm0 = fmaxf(rm0, __shfl_xor_sync(0xffffffffu, rm0, 2));
        rm1 = fmaxf(rm1, __shfl_xor_sync(0xffffffffu, rm1, 1));
        rm1 = fmaxf(rm1, __shfl_xor_sync(0xffffffffu, rm1, 2));

        const float mn0 = fmaxf(m_i[0], rm0);
        const float mn1 = fmaxf(m_i[1], rm1);
        const float corr0 = ex2(m_i[0] - mn0);
        const float corr1 = ex2(m_i[1] - mn1);
        m_i[0] = mn0; m_i[1] = mn1;

        uint32_t pa[8][4];
        float ps0 = 0.f, ps1 = 0.f;
#pragma unroll
        for (int nf = 0; nf < 8; nf++) {
            float p0 = ex2(Sf[nf][0] - mn0);
            float p1 = ex2(Sf[nf][1] - mn0);
            float p2 = ex2(Sf[nf][2] - mn1);
            float p3 = ex2(Sf[nf][3] - mn1);
            ps0 += p0 + p1;
            ps1 += p2 + p3;
            // A-fragment with k-relabel: a0=phys2t(g), a1=phys2t(g+8), a2=phys2t+1(g), a3=...
            pa[nf][0] = f2tf(p0); pa[nf][1] = f2tf(p2);
            pa[nf][2] = f2tf(p1); pa[nf][3] = f2tf(p3);
        }
        ps0 += __shfl_xor_sync(0xffffffffu, ps0, 1);
        ps0 += __shfl_xor_sync(0xffffffffu, ps0, 2);
        ps1 += __shfl_xor_sync(0xffffffffu, ps1, 1);
        ps1 += __shfl_xor_sync(0xffffffffu, ps1, 2);
        l_i[0] = l_i[0] * corr0 + ps0;
        l_i[1] = l_i[1] * corr1 + ps1;

#pragma unroll
        for (int nf = 0; nf < 8; nf++) {
            Of[nf][0] *= corr0; Of[nf][1] *= corr0;
            Of[nf][2] *= corr1; Of[nf][3] *= corr1;
        }

        // O += P @ V  (B-fragment rows 2t,2t+1 of V-transposed: LDS.64)
#pragma unroll
        for (int pc = 0; pc < 8; pc++) {
#pragma unroll
            for (int onf = 0; onf < 8; onf++) {
                uint2 vv = *(const uint2*)(sV + ((onf << 3) + g) * FS + (pc << 3) + 2 * t);
                uint32_t bfr[2] = { vv.x, vv.y };
                mma_tf32(Of[onf], pa[pc], bfr);
            }
        }
        cur ^= 1;
    }

    // normalize + write [b,l,h*hd]
    const float inv0 = 1.f / l_i[0];
    const float inv1 = 1.f / l_i[1];
    const int row0 = q0 + mrow + g;
    const int row1 = row0 + 8;
#pragma unroll
    for (int nf = 0; nf < 8; nf++) {
        const int col = h * HD_ + (nf << 3) + 2 * t;
        *(float2*)&g_attn[(size_t)(b * L_ + row0) * D_ + col] =
            make_float2(Of[nf][0] * inv0, Of[nf][1] * inv0);
        *(float2*)&g_attn[(size_t)(b * L_ + row1) * D_ + col] =
            make_float2(Of[nf][2] * inv1, Of[nf][3] * inv1);
    }
}

// ---------------- launch ----------------------------------------------------
extern "C" void kernel_launch(void* const* d_in, const int* in_sizes, int n_in,
                              void* d_out, int out_size)
{
    const float* q_in = (const float*)d_in[0];
    const float* k_in = (const float*)d_in[1];
    // d_in[2] = v_in (unused by reference), d_in[3] = mask (tril, hardcoded causal)
    const float* rope = (const float*)d_in[4];
    const float* Wq   = (const float*)d_in[5];
    const float* bq   = (const float*)d_in[6];
    const float* Wkv  = (const float*)d_in[7];
    const float* bkv  = (const float*)d_in[8];
    const float* Wp   = (const float*)d_in[9];
    const float* bp   = (const float*)d_in[10];
    float* out = (float*)d_out;

    float *qp, *kvp, *attn;
    cudaGetSymbolAddress((void**)&qp,   g_qp);
    cudaGetSymbolAddress((void**)&kvp,  g_kvp);
    cudaGetSymbolAddress((void**)&attn, g_attn);

    // 1) Q projection
    gemm_tf32_kernel<<<dim3(D_ / 128, BL_ / 128), 256>>>(q_in, Wq, bq, qp, BL_, D_, D_);
    // 2) KV projection
    gemm_tf32_kernel<<<dim3(2 * D_ / 128, BL_ / 128), 256>>>(k_in, Wkv, bkv, kvp, BL_, 2 * D_, D_);
    // 3) RoPE + split (tf32 pre-round, hd interleave) + V transpose
    rope_split_kernel<<<dim3(L_ / 64, BH_), 256>>>(rope);
    // 4) causal flash attention
    cudaFuncSetAttribute(flash_tc_kernel, cudaFuncAttributeMaxDynamicSharedMemorySize, FSMEM);
    flash_tc_kernel<<<dim3(BH_, L_ / 64), 128, FSMEM>>>();
    // 5) output projection
    gemm_tf32_kernel<<<dim3(D_ / 128, BL_ / 128), 256>>>(attn, Wp, bp, out, BL_, D_, D_);
}

// round 14
// speedup vs baseline: 4.0220x; 1.1244x over previous
#include <cuda_runtime.h>
#include <math.h>
#include <stdint.h>

// Problem constants
#define B_   4
#define L_   2048
#define D_   1024
#define H_   16
#define HD_  64
#define BH_  (B_*H_)
#define BL_  (B_*L_)
#define SCALE_ 0.125f   // 1/sqrt(64)
#define LOG2E_ 1.4426950408889634f

// ---------------- scratch (device globals; no allocation allowed) ----------
__device__ float g_qa [BL_ * D_];          // q_in, tf32 + k-interleaved
__device__ float g_ka [BL_ * D_];          // k_in, tf32 + k-interleaved
__device__ float g_wq [D_ * D_];           // Wq,  tf32, rows k-interleaved
__device__ float g_wkv[D_ * 2 * D_];       // Wkv, tf32, rows k-interleaved
__device__ float g_wp [D_ * D_];           // Wp,  tf32, rows k-interleaved
__device__ float g_qp [BL_ * D_];          // q projection  [b*l][1024] fp32
__device__ float g_kvp[BL_ * 2 * D_];      // kv projection [b*l][2048] fp32
__device__ float g_q  [BH_ * L_ * HD_];    // [b,h,l,hd(interleaved)] tf32 bits
__device__ float g_k  [BH_ * L_ * HD_];    // [b,h,l,hd(interleaved)] tf32 bits
__device__ float g_vt [BH_ * HD_ * L_];    // [b,h,hd,l] transposed, tf32 bits
__device__ float g_attn[BL_ * D_];         // [b,l,h*hd] tf32 + k-interleaved

// ---------------- tf32 helpers ---------------------------------------------
__device__ __forceinline__ uint32_t f2tf(float f) {
    uint32_t r;
    asm("cvt.rna.tf32.f32 %0, %1;" : "=r"(r) : "f"(f));
    return r;
}
__device__ __forceinline__ float f2tf_f(float f) {
    return __uint_as_float(f2tf(f));
}
__device__ __forceinline__ float ex2(float x) {
    float r;
    asm("ex2.approx.f32 %0, %1;" : "=f"(r) : "f"(x));
    return r;
}

__device__ __forceinline__ void mma_tf32(float* d, const uint32_t* a, const uint32_t* b) {
    asm volatile(
        "mma.sync.aligned.m16n8k8.row.col.f32.tf32.tf32.f32 "
        "{%0,%1,%2,%3}, {%4,%5,%6,%7}, {%8,%9}, {%0,%1,%2,%3};"
        : "+f"(d[0]), "+f"(d[1]), "+f"(d[2]), "+f"(d[3])
        : "r"(a[0]), "r"(a[1]), "r"(a[2]), "r"(a[3]), "r"(b[0]), "r"(b[1]));
}

__device__ __forceinline__ void cp16(uint32_t smem_addr, const void* gptr) {
    asm volatile("cp.async.cg.shared.global [%0], [%1], 16;" :: "r"(smem_addr), "l"(gptr));
}
#define CP_COMMIT() asm volatile("cp.async.commit_group;")
#define CP_WAIT0()  asm volatile("cp.async.wait_group 0;")

// within-8 interleave: logical w -> phys ((w&3)<<1)|(w>>2)   (phys 2t <- logical t)
__device__ __forceinline__ int ilv(int j) {
    int w = j & 7;
    return (j & ~7) | (((w & 3) << 1) | (w >> 2));
}

// ---------------- pre-convert kernels --------------------------------------
// A matrices: fp32 -> tf32, interleave cols within groups of 8.
__global__ void __launch_bounds__(256) conv_a_kernel(
    const float* __restrict__ in, float* __restrict__ out)
{
    int idx = blockIdx.x * 256 + threadIdx.x;   // one per 8 cols
    const float4* ip = (const float4*)in + (size_t)idx * 2;
    float4 a = ip[0], b = ip[1];
    // phys layout: {l0,l4,l1,l5, l2,l6,l3,l7}
    float4 o0 = make_float4(f2tf_f(a.x), f2tf_f(b.x), f2tf_f(a.y), f2tf_f(b.y));
    float4 o1 = make_float4(f2tf_f(a.z), f2tf_f(b.z), f2tf_f(a.w), f2tf_f(b.w));
    float4* op = (float4*)out + (size_t)idx * 2;
    op[0] = o0; op[1] = o1;
}

// W matrices: fp32 -> tf32, permute rows within groups of 8.
__global__ void __launch_bounds__(256) conv_w_kernel(
    const float* __restrict__ in, float* __restrict__ out, int N)
{
    int idx = blockIdx.x * 256 + threadIdx.x;   // one float4
    int n4 = N >> 2;
    int k = idx / n4;
    int c = (idx - k * n4) << 2;
    int kp = ilv(k);
    float4 v = *(const float4*)(in + (size_t)k * N + c);
    *(float4*)(out + (size_t)kp * N + c) =
        make_float4(f2tf_f(v.x), f2tf_f(v.y), f2tf_f(v.z), f2tf_f(v.w));
}

// ---------------- TF32 GEMM v2 ---------------------------------------------
// C[M,N] = A[M,K] @ W[K,N] + bias. A,W already tf32 + k-interleaved.
// 128x128 block, BK=32, 256 threads (8 warps, 2x4, 64x32 warp tile).
// 2-stage cp.async pipeline, one barrier per k-tile.
#define GAS 40    // A smem row stride (words)
#define GBS 132   // B smem row stride (words)
#define GA_WORDS (128 * GAS)          // 5120
#define GB_WORDS (32 * GBS)           // 4224
#define GSTAGE   (GA_WORDS + GB_WORDS)
#define GSMEM    (2 * GSTAGE * 4)     // 74752 bytes

__global__ void __launch_bounds__(256) gemm_tf32_kernel(
    const float* __restrict__ A, const float* __restrict__ W,
    const float* __restrict__ bias, float* __restrict__ C,
    int M, int N, int K)
{
    extern __shared__ uint32_t smg[];

    const int tid = threadIdx.x;
    const int lane = tid & 31;
    const int wid = tid >> 5;
    const int g = lane >> 2, t = lane & 3;
    const int m0 = blockIdx.y << 7, n0 = blockIdx.x << 7;
    const int wm = (wid & 1) << 6;
    const int wn = (wid >> 1) << 5;

    float acc[4][4][4];
#pragma unroll
    for (int i = 0; i < 4; i++)
#pragma unroll
        for (int j = 0; j < 4; j++)
#pragma unroll
            for (int e = 0; e < 4; e++) acc[i][j][e] = 0.f;

    // loader mapping
    const int ar = tid >> 3;             // 0..31 (+32,+64,+96)
    const int ac4 = (tid & 7) << 2;      // 0..28
    const int bk = tid >> 5;             // 0..7 (+8,+16,+24)
    const int bc4 = (tid & 31) << 2;     // 0..124

    const uint32_t sbase = (uint32_t)__cvta_generic_to_shared(smg);
    const int NT = K >> 5;

    // issue tile 0 -> stage 0
    {
        uint32_t sa = sbase;
        uint32_t sb = sbase + GA_WORDS * 4;
#pragma unroll
        for (int u = 0; u < 4; u++) {
            int r = ar + (u << 5);
            cp16(sa + (uint32_t)(r * GAS + ac4) * 4, A + (size_t)(m0 + r) * K + ac4);
        }
#pragma unroll
        for (int u = 0; u < 4; u++) {
            int r = bk + (u << 3);
            cp16(sb + (uint32_t)(r * GBS + bc4) * 4, W + (size_t)r * N + n0 + bc4);
        }
        CP_COMMIT();
    }

    int cur = 0;
    for (int ti = 0; ti < NT; ti++) {
        CP_WAIT0();
        __syncthreads();

        // issue next tile into the other stage
        if (ti + 1 < NT) {
            const int kt = (ti + 1) << 5;
            uint32_t sa = sbase + (cur ^ 1) * (GSTAGE * 4);
            uint32_t sb = sa + GA_WORDS * 4;
#pragma unroll
            for (int u = 0; u < 4; u++) {
                int r = ar + (u << 5);
                cp16(sa + (uint32_t)(r * GAS + ac4) * 4, A + (size_t)(m0 + r) * K + kt + ac4);
            }
#pragma unroll
            for (int u = 0; u < 4; u++) {
                int r = bk + (u << 3);
                cp16(sb + (uint32_t)(r * GBS + bc4) * 4, W + (size_t)(kt + r) * N + n0 + bc4);
            }
            CP_COMMIT();
        }

        const uint32_t* a_ = smg + cur * GSTAGE;
        const uint32_t* b_ = a_ + GA_WORDS;

#pragma unroll
        for (int kf = 0; kf < 4; kf++) {
            const int k0 = kf << 3;
            uint32_t af[4][4];
#pragma unroll
            for (int mf = 0; mf < 4; mf++) {
                const int r = wm + (mf << 4) + g;
                uint2 p0 = *(const uint2*)&a_[r * GAS + k0 + 2 * t];
                uint2 p1 = *(const uint2*)&a_[(r + 8) * GAS + k0 + 2 * t];
                af[mf][0] = p0.x; af[mf][1] = p1.x; af[mf][2] = p0.y; af[mf][3] = p1.y;
            }
            uint32_t bf[4][2];
#pragma unroll
            for (int nf = 0; nf < 4; nf++) {
                const int c = wn + (nf << 3) + g;
                bf[nf][0] = b_[(k0 + 2 * t) * GBS + c];
                bf[nf][1] = b_[(k0 + 2 * t + 1) * GBS + c];
            }
#pragma unroll
            for (int mf = 0; mf < 4; mf++)
#pragma unroll
                for (int nf = 0; nf < 4; nf++)
                    mma_tf32(acc[mf][nf], af[mf], bf[nf]);
        }
        cur ^= 1;
    }

    // epilogue (logical n, no interleave)
#pragma unroll
    for (int nf = 0; nf < 4; nf++) {
        const int col = n0 + wn + (nf << 3) + (t << 1);
        const float b0 = bias[col], b1 = bias[col + 1];
#pragma unroll
        for (int mf = 0; mf < 4; mf++) {
            const int row0 = m0 + wm + (mf << 4) + g;
            *(float2*)&C[(size_t)row0 * N + col] =
                make_float2(acc[mf][nf][0] + b0, acc[mf][nf][1] + b1);
            *(float2*)&C[(size_t)(row0 + 8) * N + col] =
                make_float2(acc[mf][nf][2] + b0, acc[mf][nf][3] + b1);
        }
    }
}

// ---------------- RoPE + head split + V transpose (all outputs tf32) -------
__global__ void __launch_bounds__(256) rope_split_kernel(const float* __restrict__ rope)
{
    __shared__ float sv[64][65];

    const int tid = threadIdx.x;
    const int l0 = blockIdx.x << 6;
    const int bh = blockIdx.y;
    const int b = bh >> 4, h = bh & 15;

    const int p = tid & 31;          // hd pair index
    const int lr = (tid >> 5) << 3;  // l base (8 per thread)

    const int j0 = ilv(2 * p);
    const int j1 = ilv(2 * p + 1);

#pragma unroll
    for (int u = 0; u < 8; u++) {
        const int l = lr + u;
        float2 rp = ((const float2*)rope)[(l0 + l) * 32 + p];
        const float sn = rp.x, cs = rp.y;

        const size_t rowq = (size_t)(b * L_ + l0 + l);
        float2 q = ((const float2*)g_qp)[rowq * 512 + h * 32 + p];
        const size_t kvb = rowq * 1024;
        float2 k = ((const float2*)g_kvp)[kvb + h * 32 + p];
        float2 v = ((const float2*)g_kvp)[kvb + 512 + h * 32 + p];

        float qe = q.x * cs - q.y * sn, qo = q.x * sn + q.y * cs;
        float ke = k.x * cs - k.y * sn, ko = k.x * sn + k.y * cs;

        const size_t ob = (size_t)(bh * L_ + l0 + l) * 64;
        g_q[ob + j0] = f2tf_f(qe);
        g_q[ob + j1] = f2tf_f(qo);
        g_k[ob + j0] = f2tf_f(ke);
        g_k[ob + j1] = f2tf_f(ko);

        sv[l][2 * p]     = v.x;
        sv[l][2 * p + 1] = v.y;
    }
    __syncthreads();

    const int hd = tid >> 2;
    const int c0 = (tid & 3) << 4;
    float* dst = g_vt + ((size_t)bh * 64 + hd) * L_ + l0 + c0;
#pragma unroll
    for (int j4 = 0; j4 < 4; j4++) {
        float4 o;
        o.x = f2tf_f(sv[c0 + j4 * 4 + 0][hd]);
        o.y = f2tf_f(sv[c0 + j4 * 4 + 1][hd]);
        o.z = f2tf_f(sv[c0 + j4 * 4 + 2][hd]);
        o.w = f2tf_f(sv[c0 + j4 * 4 + 3][hd]);
        *(float4*)(dst + j4 * 4) = o;
    }
}

// ---------------- causal flash attention (tf32 mma, cp.async pipelined) ----
#define FS 72
#define FTILE (64 * FS)
#define FSMEM (4 * FTILE * 4)

__global__ void __launch_bounds__(128) flash_tc_kernel()
{
    extern __shared__ float smf[];
    float* bufK[2] = { smf,             smf + 2 * FTILE };
    float* bufV[2] = { smf + FTILE,     smf + 3 * FTILE };

    const int tid = threadIdx.x;
    const int lane = tid & 31;
    const int wid = tid >> 5;
    const int g = lane >> 2, t = lane & 3;
    const int bh = blockIdx.x;
    const int qb = 31 - blockIdx.y;     // heavy blocks first
    const int q0 = qb * 64;
    const int b = bh >> 4, h = bh & 15;
    const int mrow = wid << 4;

    const float* Qg = g_q + ((size_t)bh * L_ + q0) * HD_;
    const float* Kg = g_k + (size_t)bh * L_ * HD_;
    const float* Vt = g_vt + (size_t)bh * HD_ * L_;

    const int cr = tid >> 4;
    const int cc4 = (tid & 15) << 2;

    {
        uint32_t skb = (uint32_t)__cvta_generic_to_shared(bufK[0]);
        uint32_t svb = (uint32_t)__cvta_generic_to_shared(bufV[0]);
#pragma unroll
        for (int u = 0; u < 8; u++) {
            int r = cr + (u << 3);
            cp16(skb + (uint32_t)(r * FS + cc4) * 4, Kg + (size_t)r * 64 + cc4);
            cp16(svb + (uint32_t)(r * FS + cc4) * 4, Vt + (size_t)r * L_ + cc4);
        }
        CP_COMMIT();
    }

    // stage Q into buf1 K region
#pragma unroll
    for (int u = 0; u < 8; u++) {
        int idx = tid + (u << 7);
        int r = idx >> 4;
        int c4 = (idx & 15) << 2;
        *(float4*)&bufK[1][r * FS + c4] = *(const float4*)(Qg + (size_t)r * 64 + c4);
    }
    __syncthreads();

    uint32_t qf[8][4];
#pragma unroll
    for (int kf = 0; kf < 8; kf++) {
        uint2 p0 = *(const uint2*)&bufK[1][(mrow + g) * FS + (kf << 3) + 2 * t];
        uint2 p1 = *(const uint2*)&bufK[1][(mrow + g + 8) * FS + (kf << 3) + 2 * t];
        qf[kf][0] = p0.x; qf[kf][1] = p1.x; qf[kf][2] = p0.y; qf[kf][3] = p1.y;
    }

    float Of[8][4];
    float m_i[2] = {-INFINITY, -INFINITY};
    float l_i[2] = {0.f, 0.f};
#pragma unroll
    for (int nf = 0; nf < 8; nf++)
#pragma unroll
        for (int e = 0; e < 4; e++) Of[nf][e] = 0.f;

    const float SC2 = SCALE_ * LOG2E_;
    int cur = 0;

    for (int kb = 0; kb <= qb; kb++) {
        CP_WAIT0();
        __syncthreads();

        if (kb < qb) {
            const int nn = (kb + 1) * 64;
            uint32_t skb = (uint32_t)__cvta_generic_to_shared(bufK[cur ^ 1]);
            uint32_t svb = (uint32_t)__cvta_generic_to_shared(bufV[cur ^ 1]);
#pragma unroll
            for (int u = 0; u < 8; u++) {
                int r = cr + (u << 3);
                cp16(skb + (uint32_t)(r * FS + cc4) * 4, Kg + (size_t)(nn + r) * 64 + cc4);
                cp16(svb + (uint32_t)(r * FS + cc4) * 4, Vt + (size_t)r * L_ + nn + cc4);
            }
            CP_COMMIT();
        }

        const uint32_t* sK = (const uint32_t*)bufK[cur];
        const uint32_t* sV = (const uint32_t*)bufV[cur];
        const int n0 = kb * 64;

        float Sf[8][4];
#pragma unroll
        for (int nf = 0; nf < 8; nf++) {
#pragma unroll
            for (int e = 0; e < 4; e++) Sf[nf][e] = 0.f;
            const uint32_t* krow = sK + ((nf << 3) + g) * FS + 2 * t;
#pragma unroll
            for (int kf = 0; kf < 8; kf++) {
                uint2 bv = *(const uint2*)(krow + (kf << 3));
                uint32_t bfr[2] = { bv.x, bv.y };
                mma_tf32(Sf[nf], qf[kf], bfr);
            }
        }

        const int row0 = q0 + mrow + g;
        const int row1 = row0 + 8;
        const bool diag = (kb == qb);
#pragma unroll
        for (int nf = 0; nf < 8; nf++) {
            Sf[nf][0] *= SC2; Sf[nf][1] *= SC2;
            Sf[nf][2] *= SC2; Sf[nf][3] *= SC2;
            if (diag) {
                const int c0 = n0 + (nf << 3) + 2 * t;
                if (c0 > row0)     Sf[nf][0] = -1e9f;
                if (c0 + 1 > row0) Sf[nf][1] = -1e9f;
                if (c0 > row1)     Sf[nf][2] = -1e9f;
                if (c0 + 1 > row1) Sf[nf][3] = -1e9f;
            }
        }

        float rm0 = -INFINITY, rm1 = -INFINITY;
#pragma unroll
        for (int nf = 0; nf < 8; nf++) {
            rm0 = fmaxf(rm0, fmaxf(Sf[nf][0], Sf[nf][1]));
            rm1 = fmaxf(rm1, fmaxf(Sf[nf][2], Sf[nf][3]));
        }
        rm0 = fmaxf(rm0, __shfl_xor_sync(0xffffffffu, rm0, 1));
        rm0 = fmaxf(rm0, __shfl_xor_sync(0xffffffffu, rm0, 2));
        rm1 = fmaxf(rm1, __shfl_xor_sync(0xffffffffu, rm1, 1));
        rm1 = fmaxf(rm1, __shfl_xor_sync(0xffffffffu, rm1, 2));

        const float mn0 = fmaxf(m_i[0], rm0);
        const float mn1 = fmaxf(m_i[1], rm1);
        const float corr0 = ex2(m_i[0] - mn0);
        const float corr1 = ex2(m_i[1] - mn1);
        m_i[0] = mn0; m_i[1] = mn1;

        uint32_t pa[8][4];
        float ps0 = 0.f, ps1 = 0.f;
#pragma unroll
        for (int nf = 0; nf < 8; nf++) {
            float p0 = ex2(Sf[nf][0] - mn0);
            float p1 = ex2(Sf[nf][1] - mn0);
            float p2 = ex2(Sf[nf][2] - mn1);
            float p3 = ex2(Sf[nf][3] - mn1);
            ps0 += p0 + p1;
            ps1 += p2 + p3;
            pa[nf][0] = f2tf(p0); pa[nf][1] = f2tf(p2);
            pa[nf][2] = f2tf(p1); pa[nf][3] = f2tf(p3);
        }
        ps0 += __shfl_xor_sync(0xffffffffu, ps0, 1);
        ps0 += __shfl_xor_sync(0xffffffffu, ps0, 2);
        ps1 += __shfl_xor_sync(0xffffffffu, ps1, 1);
        ps1 += __shfl_xor_sync(0xffffffffu, ps1, 2);
        l_i[0] = l_i[0] * corr0 + ps0;
        l_i[1] = l_i[1] * corr1 + ps1;

#pragma unroll
        for (int nf = 0; nf < 8; nf++) {
            Of[nf][0] *= corr0; Of[nf][1] *= corr0;
            Of[nf][2] *= corr1; Of[nf][3] *= corr1;
        }

#pragma unroll
        for (int pc = 0; pc < 8; pc++) {
#pragma unroll
            for (int onf = 0; onf < 8; onf++) {
                uint2 vv = *(const uint2*)(sV + ((onf << 3) + g) * FS + (pc << 3) + 2 * t);
                uint32_t bfr[2] = { vv.x, vv.y };
                mma_tf32(Of[onf], pa[pc], bfr);
            }
        }
        cur ^= 1;
    }

    // normalize + write g_attn as tf32 + k-interleaved (for out-proj GEMM)
    const float inv0 = 1.f / l_i[0];
    const float inv1 = 1.f / l_i[1];
    const int row0 = q0 + mrow + g;
    const int row1 = row0 + 8;
    const int pc0 = ((t & 1) << 2) | (t >> 1);   // phys(2t): {0,4,1,5}
#pragma unroll
    for (int nf = 0; nf < 8; nf++) {
        const int basec = h * HD_ + (nf << 3);
        g_attn[(size_t)(b * L_ + row0) * D_ + basec + pc0]     = f2tf_f(Of[nf][0] * inv0);
        g_attn[(size_t)(b * L_ + row0) * D_ + basec + pc0 + 2] = f2tf_f(Of[nf][1] * inv0);
        g_attn[(size_t)(b * L_ + row1) * D_ + basec + pc0]     = f2tf_f(Of[nf][2] * inv1);
        g_attn[(size_t)(b * L_ + row1) * D_ + basec + pc0 + 2] = f2tf_f(Of[nf][3] * inv1);
    }
}

// ---------------- launch ----------------------------------------------------
extern "C" void kernel_launch(void* const* d_in, const int* in_sizes, int n_in,
                              void* d_out, int out_size)
{
    const float* q_in = (const float*)d_in[0];
    const float* k_in = (const float*)d_in[1];
    // d_in[2] = v_in (unused by reference), d_in[3] = mask (tril, hardcoded causal)
    const float* rope = (const float*)d_in[4];
    const float* Wq   = (const float*)d_in[5];
    const float* bq   = (const float*)d_in[6];
    const float* Wkv  = (const float*)d_in[7];
    const float* bkv  = (const float*)d_in[8];
    const float* Wp   = (const float*)d_in[9];
    const float* bp   = (const float*)d_in[10];
    float* out = (float*)d_out;

    float *qa, *ka, *wq, *wkv, *wp, *qp, *kvp, *attn;
    cudaGetSymbolAddress((void**)&qa,   g_qa);
    cudaGetSymbolAddress((void**)&ka,   g_ka);
    cudaGetSymbolAddress((void**)&wq,   g_wq);
    cudaGetSymbolAddress((void**)&wkv,  g_wkv);
    cudaGetSymbolAddress((void**)&wp,   g_wp);
    cudaGetSymbolAddress((void**)&qp,   g_qp);
    cudaGetSymbolAddress((void**)&kvp,  g_kvp);
    cudaGetSymbolAddress((void**)&attn, g_attn);

    // 0) pre-convert inputs/weights to tf32 + k-interleave
    conv_a_kernel<<<BL_ * D_ / 8 / 256, 256>>>(q_in, qa);
    conv_a_kernel<<<BL_ * D_ / 8 / 256, 256>>>(k_in, ka);
    conv_w_kernel<<<D_ * D_ / 4 / 256, 256>>>(Wq, wq, D_);
    conv_w_kernel<<<D_ * 2 * D_ / 4 / 256, 256>>>(Wkv, wkv, 2 * D_);
    conv_w_kernel<<<D_ * D_ / 4 / 256, 256>>>(Wp, wp, D_);

    cudaFuncSetAttribute(gemm_tf32_kernel, cudaFuncAttributeMaxDynamicSharedMemorySize, GSMEM);

    // 1) Q projection
    gemm_tf32_kernel<<<dim3(D_ / 128, BL_ / 128), 256, GSMEM>>>(qa, wq, bq, qp, BL_, D_, D_);
    // 2) KV projection
    gemm_tf32_kernel<<<dim3(2 * D_ / 128, BL_ / 128), 256, GSMEM>>>(ka, wkv, bkv, kvp, BL_, 2 * D_, D_);
    // 3) RoPE + split + V transpose
    rope_split_kernel<<<dim3(L_ / 64, BH_), 256>>>(rope);
    // 4) causal flash attention
    cudaFuncSetAttribute(flash_tc_kernel, cudaFuncAttributeMaxDynamicSharedMemorySize, FSMEM);
    flash_tc_kernel<<<dim3(BH_, L_ / 64), 128, FSMEM>>>();
    // 5) output projection
    gemm_tf32_kernel<<<dim3(D_ / 128, BL_ / 128), 256, GSMEM>>>(attn, wp, bp, out, BL_, D_, D_);
}